// round 1
// baseline (speedup 1.0000x reference)
#include <cuda_runtime.h>
#include <math.h>

// Problem constants
// B=4, T=8192, C=512, W=64 -> S=128, N=B*W=256, heads=8, head_dim=64
#define BSZ   4
#define TTOT  8192
#define CDIM  512
#define WDIL  64
#define SLEN  128
#define NHEAD 8
#define HDIM  64
#define MROWS (BSZ * TTOT)   // 32768

// Scratch: Q, K, V, O  (each [MROWS, CDIM] fp32 = 64MB)
__device__ float g_Q[(size_t)MROWS * CDIM];
__device__ float g_K[(size_t)MROWS * CDIM];
__device__ float g_V[(size_t)MROWS * CDIM];
__device__ float g_O[(size_t)MROWS * CDIM];

// ---------------------------------------------------------------------------
// FP32 GEMM:  C[M,512] = A[M,512] @ B[512,512], all row-major.
// Block tile 128x128, K-tile 16, 256 threads, 8x8 per-thread microtile.
// ---------------------------------------------------------------------------
__global__ __launch_bounds__(256) void sgemm512(const float* __restrict__ A,
                                                const float* __restrict__ B,
                                                float* __restrict__ C)
{
    const int bm = blockIdx.y * 128;
    const int bn = blockIdx.x * 128;

    __shared__ float As[16][128];   // transposed: As[k][m]
    __shared__ float Bs[16][128];   // Bs[k][n]

    const int tid = threadIdx.x;
    const int tx = tid & 15;   // 0..15  -> n
    const int ty = tid >> 4;   // 0..15  -> m

    float acc[8][8];
#pragma unroll
    for (int i = 0; i < 8; i++)
#pragma unroll
        for (int j = 0; j < 8; j++) acc[i][j] = 0.0f;

    for (int k0 = 0; k0 < 512; k0 += 16) {
        // Load A tile: 128 rows x 16 cols = 512 float4
#pragma unroll
        for (int l = 0; l < 2; l++) {
            int f   = tid + l * 256;     // float4 id 0..511
            int row = f >> 2;            // 0..127
            int c4  = f & 3;             // 0..3
            float4 v = *(const float4*)(A + (size_t)(bm + row) * 512 + k0 + c4 * 4);
            As[c4 * 4 + 0][row] = v.x;
            As[c4 * 4 + 1][row] = v.y;
            As[c4 * 4 + 2][row] = v.z;
            As[c4 * 4 + 3][row] = v.w;
        }
        // Load B tile: 16 rows x 128 cols = 512 float4
#pragma unroll
        for (int l = 0; l < 2; l++) {
            int f   = tid + l * 256;
            int row = f >> 5;            // 0..15
            int c4  = f & 31;            // 0..31
            *(float4*)(&Bs[row][c4 * 4]) =
                *(const float4*)(B + (size_t)(k0 + row) * 512 + bn + c4 * 4);
        }
        __syncthreads();

#pragma unroll
        for (int kk = 0; kk < 16; kk++) {
            float a[8], b[8];
#pragma unroll
            for (int i = 0; i < 8; i++) a[i] = As[kk][ty * 8 + i];
#pragma unroll
            for (int j = 0; j < 8; j++) b[j] = Bs[kk][tx * 8 + j];
#pragma unroll
            for (int i = 0; i < 8; i++)
#pragma unroll
                for (int j = 0; j < 8; j++)
                    acc[i][j] = fmaf(a[i], b[j], acc[i][j]);
        }
        __syncthreads();
    }

#pragma unroll
    for (int i = 0; i < 8; i++) {
        size_t base = (size_t)(bm + ty * 8 + i) * 512 + bn + tx * 8;
        float4 o0 = make_float4(acc[i][0], acc[i][1], acc[i][2], acc[i][3]);
        float4 o1 = make_float4(acc[i][4], acc[i][5], acc[i][6], acc[i][7]);
        *(float4*)(C + base)     = o0;
        *(float4*)(C + base + 4) = o1;
    }
}

// ---------------------------------------------------------------------------
// Attention: one block per (n, h).  n = b*64 + w selects the dilated
// sub-sequence (rows t = s*64 + w of x-layout tensors, s = 0..127).
// RoPE applied on the fly while staging Q and K into shared memory.
// ---------------------------------------------------------------------------

// smem layout (floats):
//   Qs [128][65], Ks [128][65], Vs [128][68], Sc [128][129], rsum[128], invf[32],
//   then 128 bytes of mask.
#define QS_LD 65
#define VS_LD 68
#define SC_LD 129
#define SMEM_FLOATS (128*QS_LD + 128*QS_LD + 128*VS_LD + 128*SC_LD + 128 + 32)
#define SMEM_BYTES  (SMEM_FLOATS * 4 + 128)

__global__ __launch_bounds__(256) void attn_kernel(const float* __restrict__ Q,
                                                   const float* __restrict__ K,
                                                   const float* __restrict__ V,
                                                   const unsigned char* __restrict__ pm,
                                                   float* __restrict__ O)
{
    extern __shared__ float sm[];
    float* Qs   = sm;
    float* Ks   = Qs + 128 * QS_LD;
    float* Vs   = Ks + 128 * QS_LD;
    float* Sc   = Vs + 128 * VS_LD;
    float* rsum = Sc + 128 * SC_LD;
    float* invf = rsum + 128;
    unsigned char* mk = (unsigned char*)(invf + 32);

    const int n = blockIdx.x;       // 0..255
    const int h = blockIdx.y;       // 0..7
    const int b = n >> 6;
    const int w = n & 63;
    const int tid = threadIdx.x;
    const size_t hb = (size_t)h * HDIM;

    if (tid < 32) invf[tid] = powf(10000.0f, -(float)tid * (1.0f / 32.0f));
    if (tid < 128) mk[tid] = pm[(size_t)b * TTOT + tid * WDIL + w];
    __syncthreads();

    // Stage Q, K with RoPE (pairs d, d+32 share the angle)
    for (int e = tid; e < 128 * 32; e += 256) {
        int s = e >> 5;
        int d = e & 31;
        size_t rb = ((size_t)b * TTOT + (size_t)s * WDIL + w) * CDIM + hb;
        float ang = (float)s * invf[d];
        float si, co;
        sincosf(ang, &si, &co);
        float q0 = Q[rb + d], q1 = Q[rb + d + 32];
        Qs[s * QS_LD + d]      = q0 * co - q1 * si;
        Qs[s * QS_LD + d + 32] = q1 * co + q0 * si;
        float k0 = K[rb + d], k1 = K[rb + d + 32];
        Ks[s * QS_LD + d]      = k0 * co - k1 * si;
        Ks[s * QS_LD + d + 32] = k1 * co + k0 * si;
    }
    // Stage V (no RoPE)
    for (int e = tid; e < 128 * 64; e += 256) {
        int s = e >> 6;
        int d = e & 63;
        Vs[s * VS_LD + d] =
            V[((size_t)b * TTOT + (size_t)s * WDIL + w) * CDIM + hb + d];
    }
    __syncthreads();

    // scores[q][k] = (Q_rope[q] . K_rope[k]) * 0.125  (masked -> -FLT_MAX)
    {
        const int tx = tid & 15;    // key tile
        const int ty = tid >> 4;    // query tile
        float acc[8][8];
#pragma unroll
        for (int i = 0; i < 8; i++)
#pragma unroll
            for (int j = 0; j < 8; j++) acc[i][j] = 0.0f;

#pragma unroll 4
        for (int d = 0; d < 64; d++) {
            float a[8], bb[8];
#pragma unroll
            for (int i = 0; i < 8; i++) a[i] = Qs[(ty * 8 + i) * QS_LD + d];
#pragma unroll
            for (int j = 0; j < 8; j++) bb[j] = Ks[(tx * 8 + j) * QS_LD + d];
#pragma unroll
            for (int i = 0; i < 8; i++)
#pragma unroll
                for (int j = 0; j < 8; j++)
                    acc[i][j] = fmaf(a[i], bb[j], acc[i][j]);
        }
        const float neg = -3.4028234663852886e38f;  // finfo(float32).min
#pragma unroll
        for (int i = 0; i < 8; i++)
#pragma unroll
            for (int j = 0; j < 8; j++) {
                int col = tx * 8 + j;
                Sc[(ty * 8 + i) * SC_LD + col] =
                    mk[col] ? neg : acc[i][j] * 0.125f;
            }
    }
    __syncthreads();

    // Row softmax (thread per row); leave exp() values in Sc, 1/sum in rsum
    if (tid < 128) {
        float m = -INFINITY;
        for (int c = 0; c < 128; c++) m = fmaxf(m, Sc[tid * SC_LD + c]);
        float ssum = 0.0f;
        for (int c = 0; c < 128; c++) {
            float e = expf(Sc[tid * SC_LD + c] - m);
            Sc[tid * SC_LD + c] = e;
            ssum += e;
        }
        rsum[tid] = 1.0f / ssum;
    }
    __syncthreads();

    // out = softmax(scores) @ V  -> write to O in x-row layout
    {
        const int tx = tid & 7;     // 8 col groups of 8
        const int ty = tid >> 3;    // 32 row groups of 4
        float acc[4][8];
#pragma unroll
        for (int i = 0; i < 4; i++)
#pragma unroll
            for (int j = 0; j < 8; j++) acc[i][j] = 0.0f;

#pragma unroll 4
        for (int kk = 0; kk < 128; kk++) {
            float a[4], bb[8];
#pragma unroll
            for (int i = 0; i < 4; i++) a[i] = Sc[(ty * 4 + i) * SC_LD + kk];
#pragma unroll
            for (int j = 0; j < 8; j++) bb[j] = Vs[kk * VS_LD + tx * 8 + j];
#pragma unroll
            for (int i = 0; i < 4; i++)
#pragma unroll
                for (int j = 0; j < 8; j++)
                    acc[i][j] = fmaf(a[i], bb[j], acc[i][j]);
        }
#pragma unroll
        for (int i = 0; i < 4; i++) {
            int s = ty * 4 + i;
            float r = rsum[s];
            size_t base = ((size_t)b * TTOT + (size_t)s * WDIL + w) * CDIM + hb + tx * 8;
            float4 o0 = make_float4(acc[i][0] * r, acc[i][1] * r,
                                    acc[i][2] * r, acc[i][3] * r);
            float4 o1 = make_float4(acc[i][4] * r, acc[i][5] * r,
                                    acc[i][6] * r, acc[i][7] * r);
            *(float4*)(O + base)     = o0;
            *(float4*)(O + base + 4) = o1;
        }
    }
}

// ---------------------------------------------------------------------------
// Launch
// ---------------------------------------------------------------------------
extern "C" void kernel_launch(void* const* d_in, const int* in_sizes, int n_in,
                              void* d_out, int out_size)
{
    const float*         x  = (const float*)d_in[0];
    const unsigned char* pm = (const unsigned char*)d_in[1];
    const float*         Wq = (const float*)d_in[2];
    const float*         Wk = (const float*)d_in[3];
    const float*         Wv = (const float*)d_in[4];
    const float*         Wo = (const float*)d_in[5];
    float*               out = (float*)d_out;

    float *Qp, *Kp, *Vp, *Op;
    cudaGetSymbolAddress((void**)&Qp, g_Q);
    cudaGetSymbolAddress((void**)&Kp, g_K);
    cudaGetSymbolAddress((void**)&Vp, g_V);
    cudaGetSymbolAddress((void**)&Op, g_O);

    cudaFuncSetAttribute(attn_kernel,
                         cudaFuncAttributeMaxDynamicSharedMemorySize,
                         SMEM_BYTES);

    dim3 gg(512 / 128, MROWS / 128);   // (4, 256)
    sgemm512<<<gg, 256>>>(x, Wq, Qp);
    sgemm512<<<gg, 256>>>(x, Wk, Kp);
    sgemm512<<<gg, 256>>>(x, Wv, Vp);

    attn_kernel<<<dim3(256, NHEAD), 256, SMEM_BYTES>>>(Qp, Kp, Vp, pm, Op);

    sgemm512<<<gg, 256>>>(Op, Wo, out);
}

// round 3
// speedup vs baseline: 1.7597x; 1.7597x over previous
#include <cuda_runtime.h>
#include <cuda_bf16.h>
#include <math.h>
#include <stdint.h>

// Problem constants: B=4, T=8192, C=512, W=64 -> S=128, N=256, heads=8, hd=64
#define BSZ   4
#define TTOT  8192
#define CDIM  512
#define WDIL  64
#define NHEAD 8
#define HDIM  64
#define MROWS (BSZ * TTOT)   // 32768

// ---------------------------------------------------------------------------
// Scratch (static device memory; no allocation allowed)
// ---------------------------------------------------------------------------
__device__ __align__(1024) __nv_bfloat16 g_xhi[(size_t)MROWS * CDIM];
__device__ __align__(1024) __nv_bfloat16 g_xlo[(size_t)MROWS * CDIM];
__device__ __align__(1024) __nv_bfloat16 g_Ohi[(size_t)MROWS * CDIM];
__device__ __align__(1024) __nv_bfloat16 g_Olo[(size_t)MROWS * CDIM];
__device__ __align__(1024) __nv_bfloat16 g_Bqh[(size_t)3 * CDIM * CDIM];  // QKV W^T [1536,512] K-major
__device__ __align__(1024) __nv_bfloat16 g_Bql[(size_t)3 * CDIM * CDIM];
__device__ __align__(1024) __nv_bfloat16 g_Boh[(size_t)CDIM * CDIM];      // Wo^T [512,512] K-major
__device__ __align__(1024) __nv_bfloat16 g_Bol[(size_t)CDIM * CDIM];
__device__ float g_QKV[(size_t)3 * MROWS * CDIM];                          // Q,K,V fp32

// ---------------------------------------------------------------------------
// PTX helpers (sm_80-class only: cp.async, ldmatrix, mma.sync)
// ---------------------------------------------------------------------------
__device__ __forceinline__ uint32_t smem_to_u32(const void* p) {
    uint32_t a;
    asm("{ .reg .u64 t; cvta.to.shared.u64 t, %1; cvt.u32.u64 %0, t; }" : "=r"(a) : "l"(p));
    return a;
}
#define CP_ASYNC16(smaddr, gptr) \
    asm volatile("cp.async.cg.shared.global [%0], [%1], 16;" :: "r"(smaddr), "l"(gptr) : "memory")
#define CP_COMMIT() asm volatile("cp.async.commit_group;" ::: "memory")
template <int N> __device__ __forceinline__ void cp_wait() {
    asm volatile("cp.async.wait_group %0;" :: "n"(N) : "memory");
}
__device__ __forceinline__ void ldsm4(uint32_t* r, uint32_t addr) {
    asm volatile("ldmatrix.sync.aligned.m8n8.x4.shared.b16 {%0,%1,%2,%3}, [%4];"
                 : "=r"(r[0]), "=r"(r[1]), "=r"(r[2]), "=r"(r[3]) : "r"(addr));
}
__device__ __forceinline__ void mma16816(float* d, const uint32_t* a, const uint32_t* b) {
    asm volatile("mma.sync.aligned.m16n8k16.row.col.f32.bf16.bf16.f32 "
                 "{%0,%1,%2,%3}, {%4,%5,%6,%7}, {%8,%9}, {%0,%1,%2,%3};"
                 : "+f"(d[0]), "+f"(d[1]), "+f"(d[2]), "+f"(d[3])
                 : "r"(a[0]), "r"(a[1]), "r"(a[2]), "r"(a[3]), "r"(b[0]), "r"(b[1]));
}

// ---------------------------------------------------------------------------
// Conversion kernels (fp32 -> bf16 hi/lo split)
// ---------------------------------------------------------------------------
__global__ void conv_x(const float* __restrict__ x,
                       __nv_bfloat16* __restrict__ hi, __nv_bfloat16* __restrict__ lo) {
    size_t i = ((size_t)blockIdx.x * 256 + threadIdx.x) * 4;
    float4 v = *(const float4*)(x + i);
    float vv[4] = {v.x, v.y, v.z, v.w};
    __nv_bfloat16 h[4], l[4];
#pragma unroll
    for (int j = 0; j < 4; j++) {
        h[j] = __float2bfloat16(vv[j]);
        l[j] = __float2bfloat16(vv[j] - __bfloat162float(h[j]));
    }
    *(uint2*)(hi + i) = *(uint2*)h;
    *(uint2*)(lo + i) = *(uint2*)l;
}

__global__ void conv_wqkv(const float* __restrict__ Wq, const float* __restrict__ Wk,
                          const float* __restrict__ Wv,
                          __nv_bfloat16* __restrict__ bh, __nv_bfloat16* __restrict__ bl) {
    int idx = blockIdx.x * 256 + threadIdx.x;        // over 1536*512
    int n = idx >> 9, k = idx & 511;
    const float* W = (n < 512) ? Wq : (n < 1024) ? Wk : Wv;
    float v = W[(size_t)k * 512 + (n & 511)];
    __nv_bfloat16 h = __float2bfloat16(v);
    bh[idx] = h;
    bl[idx] = __float2bfloat16(v - __bfloat162float(h));
}

__global__ void conv_wo(const float* __restrict__ Wo,
                        __nv_bfloat16* __restrict__ bh, __nv_bfloat16* __restrict__ bl) {
    int idx = blockIdx.x * 256 + threadIdx.x;        // over 512*512
    int n = idx >> 9, k = idx & 511;
    float v = Wo[(size_t)k * 512 + n];
    __nv_bfloat16 h = __float2bfloat16(v);
    bh[idx] = h;
    bl[idx] = __float2bfloat16(v - __bfloat162float(h));
}

// ---------------------------------------------------------------------------
// Split-bf16 GEMM via mma.sync:  C = A @ B^T, 3 terms AhiBhi + AhiBlo + AloBhi.
// A rows [M,512] hi/lo, B rows [Ntot,512] hi/lo (K-major). fp32 accum in regs.
// Block 128x128, Kc=32, 8 warps (64x32 each), 3-stage cp.async pipeline.
// Smem rows padded to 80B -> conflict-free ldmatrix without swizzle.
// Output: column n routed to partition (n>>9) of C (for fused QKV); row-major 512.
// ---------------------------------------------------------------------------
#define KC 32
#define CHUNKS 16
#define ROWB 80                    // padded row bytes (32 bf16 = 64B used)
#define OP_BYTES (128 * ROWB)      // 10240
#define STAGE_BYTES (4 * OP_BYTES) // Ahi, Alo, Bhi, Blo
#define GSTAGES 3
#define GEMM_SMEM (GSTAGES * STAGE_BYTES)   // 122880

__global__ __launch_bounds__(256) void tc_gemm(const __nv_bfloat16* __restrict__ Ahi,
                                               const __nv_bfloat16* __restrict__ Alo,
                                               const __nv_bfloat16* __restrict__ Bhi,
                                               const __nv_bfloat16* __restrict__ Blo,
                                               float* __restrict__ C)
{
    extern __shared__ __align__(1024) char smv[];
    const uint32_t sb = smem_to_u32(smv);
    const int tid  = threadIdx.x;
    const int wid  = tid >> 5;
    const int lane = tid & 31;
    const int wm   = (wid >> 2) * 64;     // warp m offset (0/64)
    const int wn   = (wid & 3) * 32;      // warp n offset (0/32/64/96)

    const int m0 = blockIdx.y * 128;
    const int n0 = blockIdx.x * 128;

    float acc[4][4][4];
#pragma unroll
    for (int mi = 0; mi < 4; mi++)
#pragma unroll
        for (int ni = 0; ni < 4; ni++)
#pragma unroll
            for (int v = 0; v < 4; v++) acc[mi][ni][v] = 0.0f;

    // ---- producer ----
    auto issue = [&](int c) {
        const uint32_t base = sb + (c % GSTAGES) * STAGE_BYTES;
        const int k0 = c * KC;
#pragma unroll
        for (int rep = 0; rep < 2; rep++) {
            int idx = tid + rep * 256;           // 0..511
            int row = idx >> 2, ch = idx & 3;
            uint32_t so = (uint32_t)(row * ROWB + ch * 16);
            const size_t aoff = (size_t)(m0 + row) * CDIM + k0 + ch * 8;
            const size_t boff = (size_t)(n0 + row) * CDIM + k0 + ch * 8;
            CP_ASYNC16(base + 0 * OP_BYTES + so, Ahi + aoff);
            CP_ASYNC16(base + 1 * OP_BYTES + so, Alo + aoff);
            CP_ASYNC16(base + 2 * OP_BYTES + so, Bhi + boff);
            CP_ASYNC16(base + 3 * OP_BYTES + so, Blo + boff);
        }
        CP_COMMIT();
    };

    issue(0); issue(1); issue(2);

    // ldmatrix lane addressing: lanes 0-15 -> rows 0-15 khalf0; 16-31 -> rows, khalf1
    const uint32_t loff = (uint32_t)((lane & 15) * ROWB + (lane >> 4) * 16);

    for (int c = 0; c < CHUNKS; c++) {
        if (c < CHUNKS - 2)       cp_wait<2>();
        else if (c == CHUNKS - 2) cp_wait<1>();
        else                      cp_wait<0>();
        __syncthreads();

        const uint32_t base = sb + (c % GSTAGES) * STAGE_BYTES;
#pragma unroll
        for (int s = 0; s < 2; s++) {            // two k16 steps per chunk
            const uint32_t kb = loff + s * 32;
            uint32_t ah[4][4], al[4][4], bh[4][2], bl[4][2];
#pragma unroll
            for (int mi = 0; mi < 4; mi++) {
                uint32_t ra = base + (uint32_t)((wm + mi * 16) * ROWB) + kb;
                ldsm4(ah[mi], ra + 0 * OP_BYTES);
                ldsm4(al[mi], ra + 1 * OP_BYTES);
            }
#pragma unroll
            for (int g = 0; g < 2; g++) {
                uint32_t rb = base + (uint32_t)((wn + g * 16) * ROWB) + kb;
                uint32_t t[4];
                ldsm4(t, rb + 2 * OP_BYTES);
                bh[g*2][0] = t[0]; bh[g*2+1][0] = t[1];
                bh[g*2][1] = t[2]; bh[g*2+1][1] = t[3];
                ldsm4(t, rb + 3 * OP_BYTES);
                bl[g*2][0] = t[0]; bl[g*2+1][0] = t[1];
                bl[g*2][1] = t[2]; bl[g*2+1][1] = t[3];
            }
#pragma unroll
            for (int mi = 0; mi < 4; mi++)
#pragma unroll
                for (int ni = 0; ni < 4; ni++) {
                    mma16816(acc[mi][ni], ah[mi], bh[ni]);
                    mma16816(acc[mi][ni], ah[mi], bl[ni]);
                    mma16816(acc[mi][ni], al[mi], bh[ni]);
                }
        }
        __syncthreads();
        if (c + GSTAGES < CHUNKS) issue(c + GSTAGES);
    }

    // ---- epilogue: route column n -> partition (n>>9) ----
#pragma unroll
    for (int mi = 0; mi < 4; mi++) {
        int r = m0 + wm + mi * 16 + (lane >> 2);
#pragma unroll
        for (int ni = 0; ni < 4; ni++) {
            int gn = n0 + wn + ni * 8 + (lane & 3) * 2;
            size_t dst = (size_t)(gn >> 9) * ((size_t)MROWS * CDIM)
                       + (size_t)r * CDIM + (gn & 511);
            *(float2*)(C + dst) = make_float2(acc[mi][ni][0], acc[mi][ni][1]);
            *(float2*)(C + dst + (size_t)8 * CDIM) = make_float2(acc[mi][ni][2], acc[mi][ni][3]);
        }
    }
}

// ---------------------------------------------------------------------------
// Attention (fp32 FFMA): block per (n,h). Scores overlay Qs/Ks smem after the
// QK GEMM (acc lives in regs across a barrier) -> ~100KB smem -> 2 CTAs/SM.
// Writes bf16 hi/lo split of O for the Wo GEMM.
// ---------------------------------------------------------------------------
#define QS_LD 65
#define VS_LD 68
#define SC_LD 129
// region: QK(2*128*65) reused as Sc(128*129); then Vs, rsum, invf, mask
#define ATT_SMEM_FLOATS (2*128*QS_LD + 128*VS_LD + 128 + 32)
#define ATT_SMEM_BYTES  (ATT_SMEM_FLOATS * 4 + 128)

__global__ __launch_bounds__(256, 2) void attn_kernel(const float* __restrict__ Q,
                                                      const float* __restrict__ K,
                                                      const float* __restrict__ V,
                                                      const unsigned char* __restrict__ pm,
                                                      __nv_bfloat16* __restrict__ Ohi,
                                                      __nv_bfloat16* __restrict__ Olo)
{
    extern __shared__ float sm[];
    float* Qs   = sm;
    float* Ks   = sm + 128 * QS_LD;
    float* Sc   = sm;                       // overlay on Qs+Ks (16512 <= 16640)
    float* Vs   = sm + 2 * 128 * QS_LD;
    float* rsum = Vs + 128 * VS_LD;
    float* invf = rsum + 128;
    unsigned char* mk = (unsigned char*)(invf + 32);

    const int n = blockIdx.x, h = blockIdx.y;
    const int b = n >> 6, w = n & 63;
    const int tid = threadIdx.x;
    const size_t hb = (size_t)h * HDIM;

    if (tid < 32) invf[tid] = powf(10000.0f, -(float)tid * (1.0f / 32.0f));
    if (tid < 128) mk[tid] = pm[(size_t)b * TTOT + tid * WDIL + w];
    __syncthreads();

    for (int e = tid; e < 128 * 32; e += 256) {
        int s = e >> 5, d = e & 31;
        size_t rb = ((size_t)b * TTOT + (size_t)s * WDIL + w) * CDIM + hb;
        float ang = (float)s * invf[d];
        float si, co;
        sincosf(ang, &si, &co);
        float q0 = Q[rb + d], q1 = Q[rb + d + 32];
        Qs[s * QS_LD + d]      = q0 * co - q1 * si;
        Qs[s * QS_LD + d + 32] = q1 * co + q0 * si;
        float k0 = K[rb + d], k1 = K[rb + d + 32];
        Ks[s * QS_LD + d]      = k0 * co - k1 * si;
        Ks[s * QS_LD + d + 32] = k1 * co + k0 * si;
    }
    for (int e = tid; e < 128 * 64; e += 256) {
        int s = e >> 6, d = e & 63;
        Vs[s * VS_LD + d] = V[((size_t)b * TTOT + (size_t)s * WDIL + w) * CDIM + hb + d];
    }
    __syncthreads();

    // QK^T into registers
    const int tx = tid & 15, ty = tid >> 4;
    float acc[8][8];
#pragma unroll
    for (int i = 0; i < 8; i++)
#pragma unroll
        for (int j = 0; j < 8; j++) acc[i][j] = 0.0f;
#pragma unroll 4
    for (int d = 0; d < 64; d++) {
        float a[8], bb[8];
#pragma unroll
        for (int i = 0; i < 8; i++) a[i] = Qs[(ty * 8 + i) * QS_LD + d];
#pragma unroll
        for (int j = 0; j < 8; j++) bb[j] = Ks[(tx * 8 + j) * QS_LD + d];
#pragma unroll
        for (int i = 0; i < 8; i++)
#pragma unroll
            for (int j = 0; j < 8; j++) acc[i][j] = fmaf(a[i], bb[j], acc[i][j]);
    }
    __syncthreads();   // all reads of Qs/Ks done -> safe to overlay Sc

    const float neg = -3.4028234663852886e38f;
#pragma unroll
    for (int i = 0; i < 8; i++)
#pragma unroll
        for (int j = 0; j < 8; j++) {
            int col = tx * 8 + j;
            Sc[(ty * 8 + i) * SC_LD + col] = mk[col] ? neg : acc[i][j] * 0.125f;
        }
    __syncthreads();

    if (tid < 128) {
        float m = -INFINITY;
        for (int c = 0; c < 128; c++) m = fmaxf(m, Sc[tid * SC_LD + c]);
        float ssum = 0.0f;
        for (int c = 0; c < 128; c++) {
            float e = expf(Sc[tid * SC_LD + c] - m);
            Sc[tid * SC_LD + c] = e;
            ssum += e;
        }
        rsum[tid] = 1.0f / ssum;
    }
    __syncthreads();

    {
        const int px = tid & 7, py = tid >> 3;
        float pacc[4][8];
#pragma unroll
        for (int i = 0; i < 4; i++)
#pragma unroll
            for (int j = 0; j < 8; j++) pacc[i][j] = 0.0f;
#pragma unroll 4
        for (int kk = 0; kk < 128; kk++) {
            float a[4], bb[8];
#pragma unroll
            for (int i = 0; i < 4; i++) a[i] = Sc[(py * 4 + i) * SC_LD + kk];
#pragma unroll
            for (int j = 0; j < 8; j++) bb[j] = Vs[kk * VS_LD + px * 8 + j];
#pragma unroll
            for (int i = 0; i < 4; i++)
#pragma unroll
                for (int j = 0; j < 8; j++) pacc[i][j] = fmaf(a[i], bb[j], pacc[i][j]);
        }
#pragma unroll
        for (int i = 0; i < 4; i++) {
            int s = py * 4 + i;
            float r = rsum[s];
            size_t base = ((size_t)b * TTOT + (size_t)s * WDIL + w) * CDIM + hb + px * 8;
            __nv_bfloat16 h8[8], l8[8];
#pragma unroll
            for (int j = 0; j < 8; j++) {
                float vv = pacc[i][j] * r;
                h8[j] = __float2bfloat16(vv);
                l8[j] = __float2bfloat16(vv - __bfloat162float(h8[j]));
            }
            *(uint2*)(Ohi + base)     = *(uint2*)h8;
            *(uint2*)(Ohi + base + 4) = *(uint2*)(h8 + 4);
            *(uint2*)(Olo + base)     = *(uint2*)l8;
            *(uint2*)(Olo + base + 4) = *(uint2*)(l8 + 4);
        }
    }
}

// ---------------------------------------------------------------------------
// Launch
// ---------------------------------------------------------------------------
extern "C" void kernel_launch(void* const* d_in, const int* in_sizes, int n_in,
                              void* d_out, int out_size)
{
    const float*         x  = (const float*)d_in[0];
    const unsigned char* pm = (const unsigned char*)d_in[1];
    const float*         Wq = (const float*)d_in[2];
    const float*         Wk = (const float*)d_in[3];
    const float*         Wv = (const float*)d_in[4];
    const float*         Wo = (const float*)d_in[5];
    float*               out = (float*)d_out;

    __nv_bfloat16 *xhi, *xlo, *ohi, *olo, *bqh, *bql, *boh, *bol;
    float* qkv;
    cudaGetSymbolAddress((void**)&xhi, g_xhi);
    cudaGetSymbolAddress((void**)&xlo, g_xlo);
    cudaGetSymbolAddress((void**)&ohi, g_Ohi);
    cudaGetSymbolAddress((void**)&olo, g_Olo);
    cudaGetSymbolAddress((void**)&bqh, g_Bqh);
    cudaGetSymbolAddress((void**)&bql, g_Bql);
    cudaGetSymbolAddress((void**)&boh, g_Boh);
    cudaGetSymbolAddress((void**)&bol, g_Bol);
    cudaGetSymbolAddress((void**)&qkv, g_QKV);

    cudaFuncSetAttribute(tc_gemm, cudaFuncAttributeMaxDynamicSharedMemorySize, GEMM_SMEM);
    cudaFuncSetAttribute(attn_kernel, cudaFuncAttributeMaxDynamicSharedMemorySize, ATT_SMEM_BYTES);

    // 1) conversions
    conv_x<<<(MROWS * CDIM) / (256 * 4), 256>>>(x, xhi, xlo);
    conv_wqkv<<<(3 * CDIM * CDIM) / 256, 256>>>(Wq, Wk, Wv, bqh, bql);
    conv_wo<<<(CDIM * CDIM) / 256, 256>>>(Wo, boh, bol);

    // 2) fused QKV projection: [32768,512] x [512,1536] -> g_QKV (Q|K|V)
    tc_gemm<<<dim3(12, MROWS / 128), 256, GEMM_SMEM>>>(xhi, xlo, bqh, bql, qkv);

    // 3) attention
    const float* Qp = qkv;
    const float* Kp = qkv + (size_t)MROWS * CDIM;
    const float* Vp = qkv + (size_t)2 * MROWS * CDIM;
    attn_kernel<<<dim3(256, NHEAD), 256, ATT_SMEM_BYTES>>>(Qp, Kp, Vp, pm, ohi, olo);

    // 4) output projection -> d_out
    tc_gemm<<<dim3(4, MROWS / 128), 256, GEMM_SMEM>>>(ohi, olo, boh, bol, out);
}

// round 4
// speedup vs baseline: 1.9723x; 1.1208x over previous
#include <cuda_runtime.h>
#include <cuda_bf16.h>
#include <math.h>
#include <stdint.h>

// Problem constants: B=4, T=8192, C=512, W=64 -> S=128, N=256, heads=8, hd=64
#define BSZ   4
#define TTOT  8192
#define CDIM  512
#define WDIL  64
#define NHEAD 8
#define HDIM  64
#define MROWS (BSZ * TTOT)   // 32768

// ---------------------------------------------------------------------------
// Scratch (static device memory; no allocation allowed)
// ---------------------------------------------------------------------------
__device__ __align__(1024) __nv_bfloat16 g_xhi[(size_t)MROWS * CDIM];
__device__ __align__(1024) __nv_bfloat16 g_xlo[(size_t)MROWS * CDIM];
__device__ __align__(1024) __nv_bfloat16 g_Ohi[(size_t)MROWS * CDIM];
__device__ __align__(1024) __nv_bfloat16 g_Olo[(size_t)MROWS * CDIM];
__device__ __align__(1024) __nv_bfloat16 g_Bqh[(size_t)3 * CDIM * CDIM];  // QKV W^T [1536,512] K-major
__device__ __align__(1024) __nv_bfloat16 g_Bql[(size_t)3 * CDIM * CDIM];
__device__ __align__(1024) __nv_bfloat16 g_Boh[(size_t)CDIM * CDIM];      // Wo^T [512,512] K-major
__device__ __align__(1024) __nv_bfloat16 g_Bol[(size_t)CDIM * CDIM];
__device__ float g_QKV[(size_t)3 * MROWS * CDIM];                          // Q,K,V fp32

// ---------------------------------------------------------------------------
// PTX helpers (sm_80-class only: cp.async, ldmatrix, mma.sync)
// ---------------------------------------------------------------------------
__device__ __forceinline__ uint32_t smem_to_u32(const void* p) {
    uint32_t a;
    asm("{ .reg .u64 t; cvta.to.shared.u64 t, %1; cvt.u32.u64 %0, t; }" : "=r"(a) : "l"(p));
    return a;
}
#define CP_ASYNC16(smaddr, gptr) \
    asm volatile("cp.async.cg.shared.global [%0], [%1], 16;" :: "r"(smaddr), "l"(gptr) : "memory")
#define CP_COMMIT() asm volatile("cp.async.commit_group;" ::: "memory")
template <int N> __device__ __forceinline__ void cp_wait() {
    asm volatile("cp.async.wait_group %0;" :: "n"(N) : "memory");
}
__device__ __forceinline__ void ldsm4(uint32_t* r, uint32_t addr) {
    asm volatile("ldmatrix.sync.aligned.m8n8.x4.shared.b16 {%0,%1,%2,%3}, [%4];"
                 : "=r"(r[0]), "=r"(r[1]), "=r"(r[2]), "=r"(r[3]) : "r"(addr));
}
__device__ __forceinline__ void mma16816(float* d, const uint32_t* a, const uint32_t* b) {
    asm volatile("mma.sync.aligned.m16n8k16.row.col.f32.bf16.bf16.f32 "
                 "{%0,%1,%2,%3}, {%4,%5,%6,%7}, {%8,%9}, {%0,%1,%2,%3};"
                 : "+f"(d[0]), "+f"(d[1]), "+f"(d[2]), "+f"(d[3])
                 : "r"(a[0]), "r"(a[1]), "r"(a[2]), "r"(a[3]), "r"(b[0]), "r"(b[1]));
}
#define SWZ64(off) ((off) ^ (((off) >> 3) & 0x30))

// ---------------------------------------------------------------------------
// Conversion kernels (fp32 -> bf16 hi/lo split)
// ---------------------------------------------------------------------------
__global__ void conv_x(const float* __restrict__ x,
                       __nv_bfloat16* __restrict__ hi, __nv_bfloat16* __restrict__ lo) {
    size_t i = ((size_t)blockIdx.x * 256 + threadIdx.x) * 4;
    float4 v = *(const float4*)(x + i);
    float vv[4] = {v.x, v.y, v.z, v.w};
    __nv_bfloat16 h[4], l[4];
#pragma unroll
    for (int j = 0; j < 4; j++) {
        h[j] = __float2bfloat16(vv[j]);
        l[j] = __float2bfloat16(vv[j] - __bfloat162float(h[j]));
    }
    *(uint2*)(hi + i) = *(uint2*)h;
    *(uint2*)(lo + i) = *(uint2*)l;
}

__global__ void conv_wqkv(const float* __restrict__ Wq, const float* __restrict__ Wk,
                          const float* __restrict__ Wv,
                          __nv_bfloat16* __restrict__ bh, __nv_bfloat16* __restrict__ bl) {
    int idx = blockIdx.x * 256 + threadIdx.x;        // over 1536*512
    int n = idx >> 9, k = idx & 511;
    const float* W = (n < 512) ? Wq : (n < 1024) ? Wk : Wv;
    float v = W[(size_t)k * 512 + (n & 511)];
    __nv_bfloat16 h = __float2bfloat16(v);
    bh[idx] = h;
    bl[idx] = __float2bfloat16(v - __bfloat162float(h));
}

__global__ void conv_wo(const float* __restrict__ Wo,
                        __nv_bfloat16* __restrict__ bh, __nv_bfloat16* __restrict__ bl) {
    int idx = blockIdx.x * 256 + threadIdx.x;        // over 512*512
    int n = idx >> 9, k = idx & 511;
    float v = Wo[(size_t)k * 512 + n];
    __nv_bfloat16 h = __float2bfloat16(v);
    bh[idx] = h;
    bl[idx] = __float2bfloat16(v - __bfloat162float(h));
}

// ---------------------------------------------------------------------------
// Split-bf16 GEMM via mma.sync: C = A @ B^T, 3 terms AhiBhi + AhiBlo + AloBhi.
// Block tile 128x256, 512 threads (16 warps of 64x32), Kc=32, 3-stage cp.async
// pipeline with ONE __syncthreads per chunk. SW64-swizzled 64B smem rows.
// Output: column n routed to partition (n>>9) of C (fused QKV); row-major 512.
// ---------------------------------------------------------------------------
#define KC 32
#define CHUNKS 16
#define A_BYTES (128 * 64)                  // 8192 per operand (hi or lo)
#define B_BYTES (256 * 64)                  // 16384 per operand
#define STAGE_BYTES (2 * A_BYTES + 2 * B_BYTES)  // 49152
#define OFF_ALO  A_BYTES
#define OFF_BHI  (2 * A_BYTES)
#define OFF_BLO  (2 * A_BYTES + B_BYTES)
#define GSTAGES 3
#define GEMM_SMEM (GSTAGES * STAGE_BYTES)   // 147456

__global__ __launch_bounds__(512) void tc_gemm(const __nv_bfloat16* __restrict__ Ahi,
                                               const __nv_bfloat16* __restrict__ Alo,
                                               const __nv_bfloat16* __restrict__ Bhi,
                                               const __nv_bfloat16* __restrict__ Blo,
                                               float* __restrict__ C)
{
    extern __shared__ __align__(1024) char smv[];
    const uint32_t sb = smem_to_u32(smv);
    const int tid  = threadIdx.x;
    const int wid  = tid >> 5;
    const int lane = tid & 31;
    const int wm   = (wid & 1) * 64;          // warp m offset (0/64)
    const int wn   = (wid >> 1) * 32;         // warp n offset (0..224)

    const int m0 = blockIdx.y * 128;
    const int n0 = blockIdx.x * 256;

    float acc[4][4][4];
#pragma unroll
    for (int mi = 0; mi < 4; mi++)
#pragma unroll
        for (int ni = 0; ni < 4; ni++)
#pragma unroll
            for (int v = 0; v < 4; v++) acc[mi][ni][v] = 0.0f;

    // ---- producer: 3072 x 16B per chunk, 6 per thread ----
    auto issue = [&](int c) {
        const uint32_t base = sb + (c % GSTAGES) * STAGE_BYTES;
        const int k0 = c * KC;
        {   // A hi+lo: 128 rows x 4 chunks
            int row = tid >> 2, ch = tid & 3;
            uint32_t off = SWZ64((uint32_t)(row * 64 + ch * 16));
            size_t g = (size_t)(m0 + row) * CDIM + k0 + ch * 8;
            CP_ASYNC16(base + off, Ahi + g);
            CP_ASYNC16(base + OFF_ALO + off, Alo + g);
        }
#pragma unroll
        for (int hh = 0; hh < 2; hh++) {   // B hi+lo: 256 rows x 4 chunks
            int row = (tid >> 2) + hh * 128, ch = tid & 3;
            uint32_t off = SWZ64((uint32_t)(row * 64 + ch * 16));
            size_t g = (size_t)(n0 + row) * CDIM + k0 + ch * 8;
            CP_ASYNC16(base + OFF_BHI + off, Bhi + g);
            CP_ASYNC16(base + OFF_BLO + off, Blo + g);
        }
        CP_COMMIT();
    };

    issue(0); issue(1);

    const int lrow = lane & 15;          // ldmatrix row within 16-row group
    const int lkh  = (lane >> 4) * 16;   // 16B k-half select

    for (int c = 0; c < CHUNKS; c++) {
        if (c < CHUNKS - 1) cp_wait<1>();
        else                cp_wait<0>();
        __syncthreads();                 // chunk c ready; compute(c-1) done everywhere
        if (c + 2 < CHUNKS) issue(c + 2);  // overwrites stage consumed at c-1

        const uint32_t base = sb + (c % GSTAGES) * STAGE_BYTES;
#pragma unroll
        for (int s = 0; s < 2; s++) {    // two k16 steps per chunk
            uint32_t ah[4][4], al[4][4], bh[4][2], bl[4][2];
#pragma unroll
            for (int mi = 0; mi < 4; mi++) {
                uint32_t a = (uint32_t)((wm + mi * 16 + lrow) * 64 + s * 32 + lkh);
                a = SWZ64(a);
                ldsm4(ah[mi], base + a);
                ldsm4(al[mi], base + OFF_ALO + a);
            }
#pragma unroll
            for (int g = 0; g < 2; g++) {
                uint32_t a = (uint32_t)((wn + g * 16 + lrow) * 64 + s * 32 + lkh);
                a = SWZ64(a);
                uint32_t t[4];
                ldsm4(t, base + OFF_BHI + a);
                bh[g*2][0] = t[0]; bh[g*2+1][0] = t[1];
                bh[g*2][1] = t[2]; bh[g*2+1][1] = t[3];
                ldsm4(t, base + OFF_BLO + a);
                bl[g*2][0] = t[0]; bl[g*2+1][0] = t[1];
                bl[g*2][1] = t[2]; bl[g*2+1][1] = t[3];
            }
#pragma unroll
            for (int mi = 0; mi < 4; mi++)
#pragma unroll
                for (int ni = 0; ni < 4; ni++) {
                    mma16816(acc[mi][ni], ah[mi], bh[ni]);
                    mma16816(acc[mi][ni], ah[mi], bl[ni]);
                    mma16816(acc[mi][ni], al[mi], bh[ni]);
                }
        }
    }

    // ---- epilogue: route column n -> partition (n>>9) ----
#pragma unroll
    for (int mi = 0; mi < 4; mi++) {
        int r = m0 + wm + mi * 16 + (lane >> 2);
#pragma unroll
        for (int ni = 0; ni < 4; ni++) {
            int gn = n0 + wn + ni * 8 + (lane & 3) * 2;
            size_t dst = (size_t)(gn >> 9) * ((size_t)MROWS * CDIM)
                       + (size_t)r * CDIM + (gn & 511);
            *(float2*)(C + dst) = make_float2(acc[mi][ni][0], acc[mi][ni][1]);
            *(float2*)(C + dst + (size_t)8 * CDIM) = make_float2(acc[mi][ni][2], acc[mi][ni][3]);
        }
    }
}

// ---------------------------------------------------------------------------
// Attention (fp32 FFMA): block per (n,h). Scores overlay Qs/Ks smem after the
// QK GEMM (acc lives in regs across a barrier) -> ~100KB smem -> 2 CTAs/SM.
// Writes bf16 hi/lo split of O for the Wo GEMM.
// ---------------------------------------------------------------------------
#define QS_LD 65
#define VS_LD 68
#define SC_LD 129
#define ATT_SMEM_FLOATS (2*128*QS_LD + 128*VS_LD + 128 + 32)
#define ATT_SMEM_BYTES  (ATT_SMEM_FLOATS * 4 + 128)

__global__ __launch_bounds__(256, 2) void attn_kernel(const float* __restrict__ Q,
                                                      const float* __restrict__ K,
                                                      const float* __restrict__ V,
                                                      const unsigned char* __restrict__ pm,
                                                      __nv_bfloat16* __restrict__ Ohi,
                                                      __nv_bfloat16* __restrict__ Olo)
{
    extern __shared__ float sm[];
    float* Qs   = sm;
    float* Ks   = sm + 128 * QS_LD;
    float* Sc   = sm;                       // overlay on Qs+Ks (16512 <= 16640)
    float* Vs   = sm + 2 * 128 * QS_LD;
    float* rsum = Vs + 128 * VS_LD;
    float* invf = rsum + 128;
    unsigned char* mk = (unsigned char*)(invf + 32);

    const int n = blockIdx.x, h = blockIdx.y;
    const int b = n >> 6, w = n & 63;
    const int tid = threadIdx.x;
    const size_t hb = (size_t)h * HDIM;

    if (tid < 32) invf[tid] = powf(10000.0f, -(float)tid * (1.0f / 32.0f));
    if (tid < 128) mk[tid] = pm[(size_t)b * TTOT + tid * WDIL + w];
    __syncthreads();

    for (int e = tid; e < 128 * 32; e += 256) {
        int s = e >> 5, d = e & 31;
        size_t rb = ((size_t)b * TTOT + (size_t)s * WDIL + w) * CDIM + hb;
        float ang = (float)s * invf[d];
        float si, co;
        sincosf(ang, &si, &co);
        float q0 = Q[rb + d], q1 = Q[rb + d + 32];
        Qs[s * QS_LD + d]      = q0 * co - q1 * si;
        Qs[s * QS_LD + d + 32] = q1 * co + q0 * si;
        float k0 = K[rb + d], k1 = K[rb + d + 32];
        Ks[s * QS_LD + d]      = k0 * co - k1 * si;
        Ks[s * QS_LD + d + 32] = k1 * co + k0 * si;
    }
    for (int e = tid; e < 128 * 64; e += 256) {
        int s = e >> 6, d = e & 63;
        Vs[s * VS_LD + d] = V[((size_t)b * TTOT + (size_t)s * WDIL + w) * CDIM + hb + d];
    }
    __syncthreads();

    // QK^T into registers
    const int tx = tid & 15, ty = tid >> 4;
    float acc[8][8];
#pragma unroll
    for (int i = 0; i < 8; i++)
#pragma unroll
        for (int j = 0; j < 8; j++) acc[i][j] = 0.0f;
#pragma unroll 4
    for (int d = 0; d < 64; d++) {
        float a[8], bb[8];
#pragma unroll
        for (int i = 0; i < 8; i++) a[i] = Qs[(ty * 8 + i) * QS_LD + d];
#pragma unroll
        for (int j = 0; j < 8; j++) bb[j] = Ks[(tx * 8 + j) * QS_LD + d];
#pragma unroll
        for (int i = 0; i < 8; i++)
#pragma unroll
            for (int j = 0; j < 8; j++) acc[i][j] = fmaf(a[i], bb[j], acc[i][j]);
    }
    __syncthreads();   // all reads of Qs/Ks done -> safe to overlay Sc

    const float neg = -3.4028234663852886e38f;
#pragma unroll
    for (int i = 0; i < 8; i++)
#pragma unroll
        for (int j = 0; j < 8; j++) {
            int col = tx * 8 + j;
            Sc[(ty * 8 + i) * SC_LD + col] = mk[col] ? neg : acc[i][j] * 0.125f;
        }
    __syncthreads();

    if (tid < 128) {
        float m = -INFINITY;
        for (int c = 0; c < 128; c++) m = fmaxf(m, Sc[tid * SC_LD + c]);
        float ssum = 0.0f;
        for (int c = 0; c < 128; c++) {
            float e = expf(Sc[tid * SC_LD + c] - m);
            Sc[tid * SC_LD + c] = e;
            ssum += e;
        }
        rsum[tid] = 1.0f / ssum;
    }
    __syncthreads();

    {
        const int px = tid & 7, py = tid >> 3;
        float pacc[4][8];
#pragma unroll
        for (int i = 0; i < 4; i++)
#pragma unroll
            for (int j = 0; j < 8; j++) pacc[i][j] = 0.0f;
#pragma unroll 4
        for (int kk = 0; kk < 128; kk++) {
            float a[4], bb[8];
#pragma unroll
            for (int i = 0; i < 4; i++) a[i] = Sc[(py * 4 + i) * SC_LD + kk];
#pragma unroll
            for (int j = 0; j < 8; j++) bb[j] = Vs[kk * VS_LD + px * 8 + j];
#pragma unroll
            for (int i = 0; i < 4; i++)
#pragma unroll
                for (int j = 0; j < 8; j++) pacc[i][j] = fmaf(a[i], bb[j], pacc[i][j]);
        }
#pragma unroll
        for (int i = 0; i < 4; i++) {
            int s = py * 4 + i;
            float r = rsum[s];
            size_t base = ((size_t)b * TTOT + (size_t)s * WDIL + w) * CDIM + hb + px * 8;
            __nv_bfloat16 h8[8], l8[8];
#pragma unroll
            for (int j = 0; j < 8; j++) {
                float vv = pacc[i][j] * r;
                h8[j] = __float2bfloat16(vv);
                l8[j] = __float2bfloat16(vv - __bfloat162float(h8[j]));
            }
            *(uint2*)(Ohi + base)     = *(uint2*)h8;
            *(uint2*)(Ohi + base + 4) = *(uint2*)(h8 + 4);
            *(uint2*)(Olo + base)     = *(uint2*)l8;
            *(uint2*)(Olo + base + 4) = *(uint2*)(l8 + 4);
        }
    }
}

// ---------------------------------------------------------------------------
// Launch
// ---------------------------------------------------------------------------
extern "C" void kernel_launch(void* const* d_in, const int* in_sizes, int n_in,
                              void* d_out, int out_size)
{
    const float*         x  = (const float*)d_in[0];
    const unsigned char* pm = (const unsigned char*)d_in[1];
    const float*         Wq = (const float*)d_in[2];
    const float*         Wk = (const float*)d_in[3];
    const float*         Wv = (const float*)d_in[4];
    const float*         Wo = (const float*)d_in[5];
    float*               out = (float*)d_out;

    __nv_bfloat16 *xhi, *xlo, *ohi, *olo, *bqh, *bql, *boh, *bol;
    float* qkv;
    cudaGetSymbolAddress((void**)&xhi, g_xhi);
    cudaGetSymbolAddress((void**)&xlo, g_xlo);
    cudaGetSymbolAddress((void**)&ohi, g_Ohi);
    cudaGetSymbolAddress((void**)&olo, g_Olo);
    cudaGetSymbolAddress((void**)&bqh, g_Bqh);
    cudaGetSymbolAddress((void**)&bql, g_Bql);
    cudaGetSymbolAddress((void**)&boh, g_Boh);
    cudaGetSymbolAddress((void**)&bol, g_Bol);
    cudaGetSymbolAddress((void**)&qkv, g_QKV);

    cudaFuncSetAttribute(tc_gemm, cudaFuncAttributeMaxDynamicSharedMemorySize, GEMM_SMEM);
    cudaFuncSetAttribute(attn_kernel, cudaFuncAttributeMaxDynamicSharedMemorySize, ATT_SMEM_BYTES);

    // 1) conversions
    conv_x<<<(MROWS * CDIM) / (256 * 4), 256>>>(x, xhi, xlo);
    conv_wqkv<<<(3 * CDIM * CDIM) / 256, 256>>>(Wq, Wk, Wv, bqh, bql);
    conv_wo<<<(CDIM * CDIM) / 256, 256>>>(Wo, boh, bol);

    // 2) fused QKV projection: [32768,512] x [512,1536] -> g_QKV (Q|K|V)
    tc_gemm<<<dim3(6, MROWS / 128), 512, GEMM_SMEM>>>(xhi, xlo, bqh, bql, qkv);

    // 3) attention
    const float* Qp = qkv;
    const float* Kp = qkv + (size_t)MROWS * CDIM;
    const float* Vp = qkv + (size_t)2 * MROWS * CDIM;
    attn_kernel<<<dim3(256, NHEAD), 256, ATT_SMEM_BYTES>>>(Qp, Kp, Vp, pm, ohi, olo);

    // 4) output projection -> d_out
    tc_gemm<<<dim3(2, MROWS / 128), 512, GEMM_SMEM>>>(ohi, olo, boh, bol, out);
}

// round 6
// speedup vs baseline: 2.3353x; 1.1840x over previous
#include <cuda_runtime.h>
#include <cuda_bf16.h>
#include <math.h>
#include <stdint.h>

// Problem constants: B=4, T=8192, C=512, W=64 -> S=128, N=256, heads=8, hd=64
#define BSZ   4
#define TTOT  8192
#define CDIM  512
#define WDIL  64
#define NHEAD 8
#define HDIM  64
#define MROWS (BSZ * TTOT)   // 32768

// ---------------------------------------------------------------------------
// Scratch (static device memory; no allocation allowed)
// ---------------------------------------------------------------------------
__device__ __align__(1024) __nv_bfloat16 g_xhi[(size_t)MROWS * CDIM];
__device__ __align__(1024) __nv_bfloat16 g_xlo[(size_t)MROWS * CDIM];
__device__ __align__(1024) __nv_bfloat16 g_Ohi[(size_t)MROWS * CDIM];
__device__ __align__(1024) __nv_bfloat16 g_Olo[(size_t)MROWS * CDIM];
__device__ __align__(1024) __nv_bfloat16 g_Bqh[(size_t)3 * CDIM * CDIM];  // QKV W^T [1536,512] K-major
__device__ __align__(1024) __nv_bfloat16 g_Bql[(size_t)3 * CDIM * CDIM];
__device__ __align__(1024) __nv_bfloat16 g_Boh[(size_t)CDIM * CDIM];      // Wo^T [512,512] K-major
__device__ __align__(1024) __nv_bfloat16 g_Bol[(size_t)CDIM * CDIM];
__device__ __align__(1024) __nv_bfloat16 g_Ph[(size_t)3 * MROWS * CDIM];  // Q|K|V hi
__device__ __align__(1024) __nv_bfloat16 g_Pl[(size_t)3 * MROWS * CDIM];  // Q|K|V lo

// ---------------------------------------------------------------------------
// PTX helpers (sm_80-class only: cp.async, ldmatrix, mma.sync)
// ---------------------------------------------------------------------------
__device__ __forceinline__ uint32_t smem_to_u32(const void* p) {
    uint32_t a;
    asm("{ .reg .u64 t; cvta.to.shared.u64 t, %1; cvt.u32.u64 %0, t; }" : "=r"(a) : "l"(p));
    return a;
}
#define CP_ASYNC16(smaddr, gptr) \
    asm volatile("cp.async.cg.shared.global [%0], [%1], 16;" :: "r"(smaddr), "l"(gptr) : "memory")
#define CP_COMMIT() asm volatile("cp.async.commit_group;" ::: "memory")
template <int N> __device__ __forceinline__ void cp_wait() {
    asm volatile("cp.async.wait_group %0;" :: "n"(N) : "memory");
}
__device__ __forceinline__ void ldsm4(uint32_t* r, uint32_t addr) {
    asm volatile("ldmatrix.sync.aligned.m8n8.x4.shared.b16 {%0,%1,%2,%3}, [%4];"
                 : "=r"(r[0]), "=r"(r[1]), "=r"(r[2]), "=r"(r[3]) : "r"(addr));
}
__device__ __forceinline__ void ldsm4t(uint32_t* r, uint32_t addr) {
    asm volatile("ldmatrix.sync.aligned.m8n8.x4.trans.shared.b16 {%0,%1,%2,%3}, [%4];"
                 : "=r"(r[0]), "=r"(r[1]), "=r"(r[2]), "=r"(r[3]) : "r"(addr));
}
__device__ __forceinline__ void mma2(float* d, const uint32_t* a, uint32_t b0, uint32_t b1) {
    asm volatile("mma.sync.aligned.m16n8k16.row.col.f32.bf16.bf16.f32 "
                 "{%0,%1,%2,%3}, {%4,%5,%6,%7}, {%8,%9}, {%0,%1,%2,%3};"
                 : "+f"(d[0]), "+f"(d[1]), "+f"(d[2]), "+f"(d[3])
                 : "r"(a[0]), "r"(a[1]), "r"(a[2]), "r"(a[3]), "r"(b0), "r"(b1));
}
__device__ __forceinline__ float ex2f(float x) {
    float y; asm("ex2.approx.ftz.f32 %0, %1;" : "=f"(y) : "f"(x)); return y;
}
__device__ __forceinline__ uint32_t pack_bf(float x, float y) {
    __nv_bfloat162 t = __floats2bfloat162_rn(x, y);
    return *(uint32_t*)&t;
}
#define SWZ64(off) ((off) ^ (((off) >> 3) & 0x30))

// ---------------------------------------------------------------------------
// Conversion kernels (fp32 -> bf16 hi/lo split)
// ---------------------------------------------------------------------------
__global__ void conv_x(const float* __restrict__ x,
                       __nv_bfloat16* __restrict__ hi, __nv_bfloat16* __restrict__ lo) {
    size_t i = ((size_t)blockIdx.x * 256 + threadIdx.x) * 4;
    float4 v = *(const float4*)(x + i);
    float vv[4] = {v.x, v.y, v.z, v.w};
    __nv_bfloat16 h[4], l[4];
#pragma unroll
    for (int j = 0; j < 4; j++) {
        h[j] = __float2bfloat16(vv[j]);
        l[j] = __float2bfloat16(vv[j] - __bfloat162float(h[j]));
    }
    *(uint2*)(hi + i) = *(uint2*)h;
    *(uint2*)(lo + i) = *(uint2*)l;
}

__global__ void conv_wqkv(const float* __restrict__ Wq, const float* __restrict__ Wk,
                          const float* __restrict__ Wv,
                          __nv_bfloat16* __restrict__ bh, __nv_bfloat16* __restrict__ bl) {
    int idx = blockIdx.x * 256 + threadIdx.x;        // over 1536*512
    int n = idx >> 9, k = idx & 511;
    const float* W = (n < 512) ? Wq : (n < 1024) ? Wk : Wv;
    float v = W[(size_t)k * 512 + (n & 511)];
    __nv_bfloat16 h = __float2bfloat16(v);
    bh[idx] = h;
    bl[idx] = __float2bfloat16(v - __bfloat162float(h));
}

__global__ void conv_wo(const float* __restrict__ Wo,
                        __nv_bfloat16* __restrict__ bh, __nv_bfloat16* __restrict__ bl) {
    int idx = blockIdx.x * 256 + threadIdx.x;        // over 512*512
    int n = idx >> 9, k = idx & 511;
    float v = Wo[(size_t)k * 512 + n];
    __nv_bfloat16 h = __float2bfloat16(v);
    bh[idx] = h;
    bl[idx] = __float2bfloat16(v - __bfloat162float(h));
}

// ---------------------------------------------------------------------------
// Split-bf16 GEMM via mma.sync: C = A @ B^T, 3 terms AhiBhi + AhiBlo + AloBhi.
// Block tile 128x256, 512 threads (16 warps of 64x32), Kc=32, 4-stage cp.async
// pipeline, one __syncthreads per chunk. SW64-swizzled 64B smem rows.
// OUTF32=1: f32 row-major out. OUTF32=0: bf16 hi/lo split out, column n routed
// to partition (n>>9) (fused QKV).
// ---------------------------------------------------------------------------
#define KC 32
#define CHUNKS 16
#define A_BYTES (128 * 64)
#define B_BYTES (256 * 64)
#define STAGE_BYTES (2 * A_BYTES + 2 * B_BYTES)  // 49152
#define OFF_ALO  A_BYTES
#define OFF_BHI  (2 * A_BYTES)
#define OFF_BLO  (2 * A_BYTES + B_BYTES)
#define GSTAGES 4
#define GEMM_SMEM (GSTAGES * STAGE_BYTES)   // 196608

template<int OUTF32>
__global__ __launch_bounds__(512) void tc_gemm(const __nv_bfloat16* __restrict__ Ahi,
                                               const __nv_bfloat16* __restrict__ Alo,
                                               const __nv_bfloat16* __restrict__ Bhi,
                                               const __nv_bfloat16* __restrict__ Blo,
                                               float* __restrict__ Cf,
                                               __nv_bfloat16* __restrict__ Ch,
                                               __nv_bfloat16* __restrict__ Cl)
{
    extern __shared__ __align__(1024) char smv[];
    const uint32_t sb = smem_to_u32(smv);
    const int tid  = threadIdx.x;
    const int wid  = tid >> 5;
    const int lane = tid & 31;
    const int wm   = (wid & 1) * 64;
    const int wn   = (wid >> 1) * 32;

    const int m0 = blockIdx.y * 128;
    const int n0 = blockIdx.x * 256;

    float acc[4][4][4];
#pragma unroll
    for (int mi = 0; mi < 4; mi++)
#pragma unroll
        for (int ni = 0; ni < 4; ni++)
#pragma unroll
            for (int v = 0; v < 4; v++) acc[mi][ni][v] = 0.0f;

    auto issue = [&](int c) {
        const uint32_t base = sb + (c % GSTAGES) * STAGE_BYTES;
        const int k0 = c * KC;
        {
            int row = tid >> 2, ch = tid & 3;
            uint32_t off = SWZ64((uint32_t)(row * 64 + ch * 16));
            size_t g = (size_t)(m0 + row) * CDIM + k0 + ch * 8;
            CP_ASYNC16(base + off, Ahi + g);
            CP_ASYNC16(base + OFF_ALO + off, Alo + g);
        }
#pragma unroll
        for (int hh = 0; hh < 2; hh++) {
            int row = (tid >> 2) + hh * 128, ch = tid & 3;
            uint32_t off = SWZ64((uint32_t)(row * 64 + ch * 16));
            size_t g = (size_t)(n0 + row) * CDIM + k0 + ch * 8;
            CP_ASYNC16(base + OFF_BHI + off, Bhi + g);
            CP_ASYNC16(base + OFF_BLO + off, Blo + g);
        }
        CP_COMMIT();
    };

    issue(0); issue(1); issue(2);

    const int lrow = lane & 15;
    const int lkh  = (lane >> 4) * 16;

    for (int c = 0; c < CHUNKS; c++) {
        if (c < CHUNKS - 2)       cp_wait<2>();
        else if (c == CHUNKS - 2) cp_wait<1>();
        else                      cp_wait<0>();
        __syncthreads();
        if (c + 3 < CHUNKS) issue(c + 3);

        const uint32_t base = sb + (c % GSTAGES) * STAGE_BYTES;
#pragma unroll
        for (int s = 0; s < 2; s++) {
            uint32_t ah[4][4], al[4][4], bh[4][2], bl[4][2];
#pragma unroll
            for (int mi = 0; mi < 4; mi++) {
                uint32_t a = SWZ64((uint32_t)((wm + mi * 16 + lrow) * 64 + s * 32 + lkh));
                ldsm4(ah[mi], base + a);
                ldsm4(al[mi], base + OFF_ALO + a);
            }
#pragma unroll
            for (int g = 0; g < 2; g++) {
                uint32_t a = SWZ64((uint32_t)((wn + g * 16 + lrow) * 64 + s * 32 + lkh));
                uint32_t t[4];
                ldsm4(t, base + OFF_BHI + a);
                bh[g*2][0] = t[0]; bh[g*2+1][0] = t[1];
                bh[g*2][1] = t[2]; bh[g*2+1][1] = t[3];
                ldsm4(t, base + OFF_BLO + a);
                bl[g*2][0] = t[0]; bl[g*2+1][0] = t[1];
                bl[g*2][1] = t[2]; bl[g*2+1][1] = t[3];
            }
#pragma unroll
            for (int mi = 0; mi < 4; mi++)
#pragma unroll
                for (int ni = 0; ni < 4; ni++) {
                    mma2(acc[mi][ni], ah[mi], bh[ni][0], bh[ni][1]);
                    mma2(acc[mi][ni], ah[mi], bl[ni][0], bl[ni][1]);
                    mma2(acc[mi][ni], al[mi], bh[ni][0], bh[ni][1]);
                }
        }
    }

#pragma unroll
    for (int mi = 0; mi < 4; mi++) {
        int r = m0 + wm + mi * 16 + (lane >> 2);
#pragma unroll
        for (int ni = 0; ni < 4; ni++) {
            int gn = n0 + wn + ni * 8 + (lane & 3) * 2;
            if (OUTF32) {
                size_t dst = (size_t)r * CDIM + gn;
                *(float2*)(Cf + dst) = make_float2(acc[mi][ni][0], acc[mi][ni][1]);
                *(float2*)(Cf + dst + (size_t)8 * CDIM) = make_float2(acc[mi][ni][2], acc[mi][ni][3]);
            } else {
                size_t dst = (size_t)(gn >> 9) * ((size_t)MROWS * CDIM)
                           + (size_t)r * CDIM + (gn & 511);
#pragma unroll
                for (int half = 0; half < 2; half++) {
                    float x0 = acc[mi][ni][half * 2], x1 = acc[mi][ni][half * 2 + 1];
                    __nv_bfloat16 h0 = __float2bfloat16(x0), h1 = __float2bfloat16(x1);
                    __nv_bfloat162 hv; hv.x = h0; hv.y = h1;
                    __nv_bfloat162 lv;
                    lv.x = __float2bfloat16(x0 - __bfloat162float(h0));
                    lv.y = __float2bfloat16(x1 - __bfloat162float(h1));
                    size_t d2 = dst + (size_t)(half * 8) * CDIM;
                    *(__nv_bfloat162*)(Ch + d2) = hv;
                    *(__nv_bfloat162*)(Cl + d2) = lv;
                }
            }
        }
    }
}

// ---------------------------------------------------------------------------
// HMMA attention: block per (n,h), 256 threads = 8 warps, each warp 16 q-rows.
// Split-bf16 3-term for QK^T and P·V. Softmax in register fragments with
// quad shuffles; exp2 with log2(e)*0.125 folded into Q. Output bf16 hi/lo.
// Smem tiles: 144B rows (72 bf16) -> conflict-free ldmatrix, no swizzle.
// ---------------------------------------------------------------------------
#define AT_LD 72
#define AT_ROWB 144
#define AT_TILE (128 * AT_ROWB)     // 18432
#define OFF_QHs 0
#define OFF_QLs (1 * AT_TILE)
#define OFF_KHs (2 * AT_TILE)
#define OFF_KLs (3 * AT_TILE)
#define OFF_VHs (4 * AT_TILE)
#define OFF_VLs (5 * AT_TILE)
#define OFF_MKs (6 * AT_TILE)       // 110592, 128 bytes
#define OFF_INV (OFF_MKs + 128)     // 32 floats
#define ATT2_SMEM (OFF_INV + 128)   // 110848

__global__ __launch_bounds__(256, 2) void attn2(const __nv_bfloat16* __restrict__ Ph,
                                                const __nv_bfloat16* __restrict__ Pl,
                                                const unsigned char* __restrict__ pm,
                                                __nv_bfloat16* __restrict__ Ohi,
                                                __nv_bfloat16* __restrict__ Olo)
{
    extern __shared__ __align__(1024) char smc[];
    const uint32_t sb = smem_to_u32(smc);
    float* invf = (float*)(smc + OFF_INV);
    unsigned char* mk = (unsigned char*)(smc + OFF_MKs);

    const int tid  = threadIdx.x;
    const int lane = tid & 31;
    const int wid  = tid >> 5;
    const int n = blockIdx.x, h = blockIdx.y;
    const int b = n >> 6, w = n & 63;

    const __nv_bfloat16* Qh_g = Ph;
    const __nv_bfloat16* Ql_g = Pl;
    const __nv_bfloat16* Kh_g = Ph + (size_t)MROWS * CDIM;
    const __nv_bfloat16* Kl_g = Pl + (size_t)MROWS * CDIM;
    const __nv_bfloat16* Vh_g = Ph + (size_t)2 * MROWS * CDIM;
    const __nv_bfloat16* Vl_g = Pl + (size_t)2 * MROWS * CDIM;

    if (tid < 32) invf[tid] = powf(10000.0f, -(float)tid * (1.0f / 32.0f));
    if (tid < 128) mk[tid] = pm[(size_t)b * TTOT + tid * WDIL + w];

    // V tiles via cp.async: 128 rows x 64 dims x 2B = 16KB per tile
    // = 1024 chunks of 16B (8 chunks per 128B row)
    for (int t = tid; t < 1024; t += 256) {
        int row = t >> 3, ch = t & 7;
        size_t g = ((size_t)(b * TTOT + row * WDIL + w)) * CDIM + h * HDIM + ch * 8;
        CP_ASYNC16(sb + OFF_VHs + row * AT_ROWB + ch * 16, Vh_g + g);
        CP_ASYNC16(sb + OFF_VLs + row * AT_ROWB + ch * 16, Vl_g + g);
    }
    CP_COMMIT();
    __syncthreads();   // invf + mask ready

    // Q/K staging with RoPE; fold 0.125*log2(e) into Q
    const float QSCALE = 0.125f * 1.44269504088896f;
    __nv_bfloat16* sQh = (__nv_bfloat16*)(smc + OFF_QHs);
    __nv_bfloat16* sQl = (__nv_bfloat16*)(smc + OFF_QLs);
    __nv_bfloat16* sKh = (__nv_bfloat16*)(smc + OFF_KHs);
    __nv_bfloat16* sKl = (__nv_bfloat16*)(smc + OFF_KLs);
    for (int e = tid; e < 128 * 32; e += 256) {
        int s = e >> 5, d = e & 31;
        size_t rb = ((size_t)(b * TTOT + s * WDIL + w)) * CDIM + h * HDIM;
        float ang = (float)s * invf[d];
        float si, co;
        sincosf(ang, &si, &co);
        float q0 = __bfloat162float(Qh_g[rb + d]) + __bfloat162float(Ql_g[rb + d]);
        float q1 = __bfloat162float(Qh_g[rb + d + 32]) + __bfloat162float(Ql_g[rb + d + 32]);
        float k0 = __bfloat162float(Kh_g[rb + d]) + __bfloat162float(Kl_g[rb + d]);
        float k1 = __bfloat162float(Kh_g[rb + d + 32]) + __bfloat162float(Kl_g[rb + d + 32]);
        float qa = (q0 * co - q1 * si) * QSCALE;
        float qb = (q1 * co + q0 * si) * QSCALE;
        float ka = k0 * co - k1 * si;
        float kb = k1 * co + k0 * si;
        __nv_bfloat16 t;
        t = __float2bfloat16(qa); sQh[s * AT_LD + d] = t;
        sQl[s * AT_LD + d] = __float2bfloat16(qa - __bfloat162float(t));
        t = __float2bfloat16(qb); sQh[s * AT_LD + d + 32] = t;
        sQl[s * AT_LD + d + 32] = __float2bfloat16(qb - __bfloat162float(t));
        t = __float2bfloat16(ka); sKh[s * AT_LD + d] = t;
        sKl[s * AT_LD + d] = __float2bfloat16(ka - __bfloat162float(t));
        t = __float2bfloat16(kb); sKh[s * AT_LD + d + 32] = t;
        sKl[s * AT_LD + d + 32] = __float2bfloat16(kb - __bfloat162float(t));
    }
    cp_wait<0>();
    __syncthreads();

    // ===== QK^T: warp tile m16 x n128 x k64 =====
    const int qr = wid * 16;
    float c[16][4];
#pragma unroll
    for (int j = 0; j < 16; j++)
#pragma unroll
        for (int v = 0; v < 4; v++) c[j][v] = 0.0f;

#pragma unroll
    for (int kk = 0; kk < 4; kk++) {
        uint32_t ah[4], al[4];
        uint32_t abase = sb + OFF_QHs + (uint32_t)((qr + (lane & 15)) * AT_ROWB)
                       + kk * 32 + (lane >> 4) * 16;
        ldsm4(ah, abase);
        ldsm4(al, abase + AT_TILE);
#pragma unroll
        for (int g = 0; g < 8; g++) {
            uint32_t kaddr = sb + OFF_KHs + (uint32_t)((g * 16 + (lane & 15)) * AT_ROWB)
                           + kk * 32 + (lane >> 4) * 16;
            uint32_t th[4], tl[4];
            ldsm4(th, kaddr);
            ldsm4(tl, kaddr + AT_TILE);
            mma2(c[2*g],   ah, th[0], th[2]);
            mma2(c[2*g],   ah, tl[0], tl[2]);
            mma2(c[2*g],   al, th[0], th[2]);
            mma2(c[2*g+1], ah, th[1], th[3]);
            mma2(c[2*g+1], ah, tl[1], tl[3]);
            mma2(c[2*g+1], al, th[1], th[3]);
        }
    }

    // ===== mask + softmax (rows spread over lane quads) =====
    float mx0 = -1e30f, mx1 = -1e30f;
#pragma unroll
    for (int j = 0; j < 16; j++) {
        int n0 = j * 8 + (lane & 3) * 2;
        if (mk[n0])     { c[j][0] = -1e30f; c[j][2] = -1e30f; }
        if (mk[n0 + 1]) { c[j][1] = -1e30f; c[j][3] = -1e30f; }
        mx0 = fmaxf(mx0, fmaxf(c[j][0], c[j][1]));
        mx1 = fmaxf(mx1, fmaxf(c[j][2], c[j][3]));
    }
    mx0 = fmaxf(mx0, __shfl_xor_sync(~0u, mx0, 1));
    mx0 = fmaxf(mx0, __shfl_xor_sync(~0u, mx0, 2));
    mx1 = fmaxf(mx1, __shfl_xor_sync(~0u, mx1, 1));
    mx1 = fmaxf(mx1, __shfl_xor_sync(~0u, mx1, 2));
    float s0 = 0.0f, s1 = 0.0f;
#pragma unroll
    for (int j = 0; j < 16; j++) {
        c[j][0] = ex2f(c[j][0] - mx0); s0 += c[j][0];
        c[j][1] = ex2f(c[j][1] - mx0); s0 += c[j][1];
        c[j][2] = ex2f(c[j][2] - mx1); s1 += c[j][2];
        c[j][3] = ex2f(c[j][3] - mx1); s1 += c[j][3];
    }
    s0 += __shfl_xor_sync(~0u, s0, 1); s0 += __shfl_xor_sync(~0u, s0, 2);
    s1 += __shfl_xor_sync(~0u, s1, 1); s1 += __shfl_xor_sync(~0u, s1, 2);
    const float inv0 = 1.0f / s0, inv1 = 1.0f / s1;

    // ===== P @ V: m16 x n64 x k128 =====
    float o[8][4];
#pragma unroll
    for (int j = 0; j < 8; j++)
#pragma unroll
        for (int v = 0; v < 4; v++) o[j][v] = 0.0f;

#pragma unroll
    for (int t = 0; t < 8; t++) {
        // A fragments from c tiles 2t, 2t+1 (hi + lo)
        uint32_t pah[4], pal[4];
#pragma unroll
        for (int q = 0; q < 4; q++) {
            int jt = 2 * t + (q >> 1);
            float x0 = c[jt][(q & 1) * 2], x1 = c[jt][(q & 1) * 2 + 1];
            __nv_bfloat16 h0 = __float2bfloat16(x0), h1 = __float2bfloat16(x1);
            __nv_bfloat162 hv; hv.x = h0; hv.y = h1;
            pah[q] = *(uint32_t*)&hv;
            pal[q] = pack_bf(x0 - __bfloat162float(h0), x1 - __bfloat162float(h1));
        }
#pragma unroll
        for (int gg = 0; gg < 4; gg++) {
            uint32_t vaddr = sb + OFF_VHs
                + (uint32_t)((t * 16 + (lane & 7) + ((lane >> 3) & 1) * 8) * AT_ROWB)
                + gg * 32 + (lane >> 4) * 16;
            uint32_t vh[4], vl[4];
            ldsm4t(vh, vaddr);
            ldsm4t(vl, vaddr + AT_TILE);
            mma2(o[2*gg],   pah, vh[0], vh[1]);
            mma2(o[2*gg],   pah, vl[0], vl[1]);
            mma2(o[2*gg],   pal, vh[0], vh[1]);
            mma2(o[2*gg+1], pah, vh[2], vh[3]);
            mma2(o[2*gg+1], pah, vl[2], vl[3]);
            mma2(o[2*gg+1], pal, vh[2], vh[3]);
        }
    }

    // ===== epilogue: normalize, split hi/lo, store =====
    const int r0 = qr + (lane >> 2);
#pragma unroll
    for (int j2 = 0; j2 < 8; j2++) {
        int d0 = j2 * 8 + (lane & 3) * 2;
        size_t g0 = ((size_t)(b * TTOT + r0 * WDIL + w)) * CDIM + h * HDIM + d0;
        size_t g1 = g0 + (size_t)8 * WDIL * CDIM;
        float y0 = o[j2][0] * inv0, y1 = o[j2][1] * inv0;
        __nv_bfloat16 h0 = __float2bfloat16(y0), h1 = __float2bfloat16(y1);
        __nv_bfloat162 hv; hv.x = h0; hv.y = h1;
        __nv_bfloat162 lv;
        lv.x = __float2bfloat16(y0 - __bfloat162float(h0));
        lv.y = __float2bfloat16(y1 - __bfloat162float(h1));
        *(__nv_bfloat162*)(Ohi + g0) = hv;
        *(__nv_bfloat162*)(Olo + g0) = lv;
        float y2 = o[j2][2] * inv1, y3 = o[j2][3] * inv1;
        h0 = __float2bfloat16(y2); h1 = __float2bfloat16(y3);
        hv.x = h0; hv.y = h1;
        lv.x = __float2bfloat16(y2 - __bfloat162float(h0));
        lv.y = __float2bfloat16(y3 - __bfloat162float(h1));
        *(__nv_bfloat162*)(Ohi + g1) = hv;
        *(__nv_bfloat162*)(Olo + g1) = lv;
    }
}

// ---------------------------------------------------------------------------
// Launch
// ---------------------------------------------------------------------------
extern "C" void kernel_launch(void* const* d_in, const int* in_sizes, int n_in,
                              void* d_out, int out_size)
{
    const float*         x  = (const float*)d_in[0];
    const unsigned char* pm = (const unsigned char*)d_in[1];
    const float*         Wq = (const float*)d_in[2];
    const float*         Wk = (const float*)d_in[3];
    const float*         Wv = (const float*)d_in[4];
    const float*         Wo = (const float*)d_in[5];
    float*               out = (float*)d_out;

    __nv_bfloat16 *xhi, *xlo, *ohi, *olo, *bqh, *bql, *boh, *bol, *ph, *pl;
    cudaGetSymbolAddress((void**)&xhi, g_xhi);
    cudaGetSymbolAddress((void**)&xlo, g_xlo);
    cudaGetSymbolAddress((void**)&ohi, g_Ohi);
    cudaGetSymbolAddress((void**)&olo, g_Olo);
    cudaGetSymbolAddress((void**)&bqh, g_Bqh);
    cudaGetSymbolAddress((void**)&bql, g_Bql);
    cudaGetSymbolAddress((void**)&boh, g_Boh);
    cudaGetSymbolAddress((void**)&bol, g_Bol);
    cudaGetSymbolAddress((void**)&ph, g_Ph);
    cudaGetSymbolAddress((void**)&pl, g_Pl);

    cudaFuncSetAttribute(tc_gemm<0>, cudaFuncAttributeMaxDynamicSharedMemorySize, GEMM_SMEM);
    cudaFuncSetAttribute(tc_gemm<1>, cudaFuncAttributeMaxDynamicSharedMemorySize, GEMM_SMEM);
    cudaFuncSetAttribute(attn2, cudaFuncAttributeMaxDynamicSharedMemorySize, ATT2_SMEM);

    // 1) conversions
    conv_x<<<(MROWS * CDIM) / (256 * 4), 256>>>(x, xhi, xlo);
    conv_wqkv<<<(3 * CDIM * CDIM) / 256, 256>>>(Wq, Wk, Wv, bqh, bql);
    conv_wo<<<(CDIM * CDIM) / 256, 256>>>(Wo, boh, bol);

    // 2) fused QKV projection -> bf16 hi/lo (Q|K|V partitions)
    tc_gemm<0><<<dim3(6, MROWS / 128), 512, GEMM_SMEM>>>(xhi, xlo, bqh, bql,
                                                         nullptr, ph, pl);

    // 3) HMMA attention -> bf16 hi/lo O
    attn2<<<dim3(256, NHEAD), 256, ATT2_SMEM>>>(ph, pl, pm, ohi, olo);

    // 4) output projection -> d_out (f32)
    tc_gemm<1><<<dim3(2, MROWS / 128), 512, GEMM_SMEM>>>(ohi, olo, boh, bol,
                                                         out, nullptr, nullptr);
}

// round 7
// speedup vs baseline: 3.0234x; 1.2946x over previous
#include <cuda_runtime.h>
#include <cuda_fp16.h>
#include <math.h>
#include <stdint.h>

// Problem constants: B=4, T=8192, C=512, W=64 -> S=128, N=256, heads=8, hd=64
#define BSZ   4
#define TTOT  8192
#define CDIM  512
#define WDIL  64
#define NHEAD 8
#define HDIM  64
#define MROWS (BSZ * TTOT)   // 32768

// ---------------------------------------------------------------------------
// Scratch (static device memory; no allocation allowed)
// ---------------------------------------------------------------------------
__device__ __align__(1024) __half g_xhi[(size_t)MROWS * CDIM];
__device__ __align__(1024) __half g_xlo[(size_t)MROWS * CDIM];
__device__ __align__(1024) __half g_Ohi[(size_t)MROWS * CDIM];
__device__ __align__(1024) __half g_Olo[(size_t)MROWS * CDIM];
__device__ __align__(1024) __half g_Bq[(size_t)3 * CDIM * CDIM];   // QKV W^T [1536,512] K-major, fp16
__device__ __align__(1024) __half g_Bo[(size_t)CDIM * CDIM];       // Wo^T [512,512] K-major, fp16
__device__ __align__(1024) __half g_Ph[(size_t)3 * MROWS * CDIM];  // Q|K|V hi
__device__ __align__(1024) __half g_Pl[(size_t)3 * MROWS * CDIM];  // Q|K|V lo

// ---------------------------------------------------------------------------
// PTX helpers (sm_80-class only: cp.async, ldmatrix, mma.sync)
// ---------------------------------------------------------------------------
__device__ __forceinline__ uint32_t smem_to_u32(const void* p) {
    uint32_t a;
    asm("{ .reg .u64 t; cvta.to.shared.u64 t, %1; cvt.u32.u64 %0, t; }" : "=r"(a) : "l"(p));
    return a;
}
#define CP_ASYNC16(smaddr, gptr) \
    asm volatile("cp.async.cg.shared.global [%0], [%1], 16;" :: "r"(smaddr), "l"(gptr) : "memory")
#define CP_COMMIT() asm volatile("cp.async.commit_group;" ::: "memory")
template <int N> __device__ __forceinline__ void cp_wait() {
    asm volatile("cp.async.wait_group %0;" :: "n"(N) : "memory");
}
__device__ __forceinline__ void ldsm4(uint32_t* r, uint32_t addr) {
    asm volatile("ldmatrix.sync.aligned.m8n8.x4.shared.b16 {%0,%1,%2,%3}, [%4];"
                 : "=r"(r[0]), "=r"(r[1]), "=r"(r[2]), "=r"(r[3]) : "r"(addr));
}
__device__ __forceinline__ void ldsm4t(uint32_t* r, uint32_t addr) {
    asm volatile("ldmatrix.sync.aligned.m8n8.x4.trans.shared.b16 {%0,%1,%2,%3}, [%4];"
                 : "=r"(r[0]), "=r"(r[1]), "=r"(r[2]), "=r"(r[3]) : "r"(addr));
}
__device__ __forceinline__ void mma2(float* d, const uint32_t* a, uint32_t b0, uint32_t b1) {
    asm volatile("mma.sync.aligned.m16n8k16.row.col.f32.f16.f16.f32 "
                 "{%0,%1,%2,%3}, {%4,%5,%6,%7}, {%8,%9}, {%0,%1,%2,%3};"
                 : "+f"(d[0]), "+f"(d[1]), "+f"(d[2]), "+f"(d[3])
                 : "r"(a[0]), "r"(a[1]), "r"(a[2]), "r"(a[3]), "r"(b0), "r"(b1));
}
__device__ __forceinline__ float ex2f(float x) {
    float y; asm("ex2.approx.ftz.f32 %0, %1;" : "=f"(y) : "f"(x)); return y;
}
__device__ __forceinline__ uint32_t packh(float x, float y) {
    __half2 t = __floats2half2_rn(x, y);
    return *(uint32_t*)&t;
}
#define SWZ64(off) ((off) ^ (((off) >> 3) & 0x30))

// ---------------------------------------------------------------------------
// Conversion kernels
// ---------------------------------------------------------------------------
__global__ void conv_x(const float* __restrict__ x,
                       __half* __restrict__ hi, __half* __restrict__ lo) {
    size_t i = ((size_t)blockIdx.x * 256 + threadIdx.x) * 4;
    float4 v = *(const float4*)(x + i);
    float vv[4] = {v.x, v.y, v.z, v.w};
    __half h[4], l[4];
#pragma unroll
    for (int j = 0; j < 4; j++) {
        h[j] = __float2half_rn(vv[j]);
        l[j] = __float2half_rn(vv[j] - __half2float(h[j]));
    }
    *(uint2*)(hi + i) = *(uint2*)h;
    *(uint2*)(lo + i) = *(uint2*)l;
}

__global__ void conv_wqkv(const float* __restrict__ Wq, const float* __restrict__ Wk,
                          const float* __restrict__ Wv, __half* __restrict__ bq) {
    int idx = blockIdx.x * 256 + threadIdx.x;        // over 1536*512
    int n = idx >> 9, k = idx & 511;
    const float* W = (n < 512) ? Wq : (n < 1024) ? Wk : Wv;
    bq[idx] = __float2half_rn(W[(size_t)k * 512 + (n & 511)]);
}

__global__ void conv_wo(const float* __restrict__ Wo, __half* __restrict__ bo) {
    int idx = blockIdx.x * 256 + threadIdx.x;        // over 512*512
    int n = idx >> 9, k = idx & 511;
    bo[idx] = __float2half_rn(Wo[(size_t)k * 512 + n]);
}

// ---------------------------------------------------------------------------
// fp16 2-term GEMM via mma.sync: C = (Ahi+Alo) @ Bfp16^T.
// Tile 128x128, 256 threads (8 warps of 64x32), Kc=32, 4-stage cp.async
// pipeline, one __syncthreads per chunk, SW64 swizzle, 2 CTAs/SM.
// OUTF32=1: f32 row-major out. OUTF32=0: fp16 hi/lo out, column n routed to
// partition (n>>9) (fused QKV).
// ---------------------------------------------------------------------------
#define KC 32
#define CHUNKS 16
#define GA_BYTES (128 * 64)                    // 8192 per A version
#define STAGE_BYTES (3 * GA_BYTES)             // Ahi, Alo, B = 24576
#define OFF_ALO  GA_BYTES
#define OFF_B    (2 * GA_BYTES)
#define GSTAGES 4
#define GEMM_SMEM (GSTAGES * STAGE_BYTES)      // 98304

template<int OUTF32>
__global__ __launch_bounds__(256, 2) void tc_gemm(const __half* __restrict__ Ahi,
                                                  const __half* __restrict__ Alo,
                                                  const __half* __restrict__ Bw,
                                                  float* __restrict__ Cf,
                                                  __half* __restrict__ Ch,
                                                  __half* __restrict__ Cl)
{
    extern __shared__ __align__(1024) char smv[];
    const uint32_t sb = smem_to_u32(smv);
    const int tid  = threadIdx.x;
    const int wid  = tid >> 5;
    const int lane = tid & 31;
    const int wm   = (wid & 1) * 64;
    const int wn   = (wid >> 1) * 32;

    const int m0 = blockIdx.y * 128;
    const int n0 = blockIdx.x * 128;

    float acc[4][4][4];
#pragma unroll
    for (int mi = 0; mi < 4; mi++)
#pragma unroll
        for (int ni = 0; ni < 4; ni++)
#pragma unroll
            for (int v = 0; v < 4; v++) acc[mi][ni][v] = 0.0f;

    // producer: A 1024 chunks (hi+lo) + B 512 chunks = 6 cp.async/thread
    auto issue = [&](int c) {
        const uint32_t base = sb + (c % GSTAGES) * STAGE_BYTES;
        const int k0 = c * KC;
        const int row = tid >> 1;
        const int ch2 = (tid & 1) * 2;
#pragma unroll
        for (int j = 0; j < 2; j++) {
            int ch = ch2 + j;
            uint32_t off = SWZ64((uint32_t)(row * 64 + ch * 16));
            size_t ga = (size_t)(m0 + row) * CDIM + k0 + ch * 8;
            size_t gb = (size_t)(n0 + row) * CDIM + k0 + ch * 8;
            CP_ASYNC16(base + off, Ahi + ga);
            CP_ASYNC16(base + OFF_ALO + off, Alo + ga);
            CP_ASYNC16(base + OFF_B + off, Bw + gb);
        }
        CP_COMMIT();
    };

    issue(0); issue(1); issue(2);

    const int lrow = lane & 15;
    const int lkh  = (lane >> 4) * 16;

    for (int c = 0; c < CHUNKS; c++) {
        if (c < CHUNKS - 2)       cp_wait<2>();
        else if (c == CHUNKS - 2) cp_wait<1>();
        else                      cp_wait<0>();
        __syncthreads();
        if (c + 3 < CHUNKS) issue(c + 3);

        const uint32_t base = sb + (c % GSTAGES) * STAGE_BYTES;
#pragma unroll
        for (int s = 0; s < 2; s++) {
            uint32_t ah[4][4], al[4][4], bf[4][2];
#pragma unroll
            for (int mi = 0; mi < 4; mi++) {
                uint32_t a = SWZ64((uint32_t)((wm + mi * 16 + lrow) * 64 + s * 32 + lkh));
                ldsm4(ah[mi], base + a);
                ldsm4(al[mi], base + OFF_ALO + a);
            }
#pragma unroll
            for (int g = 0; g < 2; g++) {
                uint32_t a = SWZ64((uint32_t)((wn + g * 16 + lrow) * 64 + s * 32 + lkh));
                uint32_t t[4];
                ldsm4(t, base + OFF_B + a);
                bf[g*2][0] = t[0]; bf[g*2+1][0] = t[1];
                bf[g*2][1] = t[2]; bf[g*2+1][1] = t[3];
            }
#pragma unroll
            for (int mi = 0; mi < 4; mi++)
#pragma unroll
                for (int ni = 0; ni < 4; ni++) {
                    mma2(acc[mi][ni], ah[mi], bf[ni][0], bf[ni][1]);
                    mma2(acc[mi][ni], al[mi], bf[ni][0], bf[ni][1]);
                }
        }
    }

#pragma unroll
    for (int mi = 0; mi < 4; mi++) {
        int r = m0 + wm + mi * 16 + (lane >> 2);
#pragma unroll
        for (int ni = 0; ni < 4; ni++) {
            int gn = n0 + wn + ni * 8 + (lane & 3) * 2;
            if (OUTF32) {
                size_t dst = (size_t)r * CDIM + gn;
                *(float2*)(Cf + dst) = make_float2(acc[mi][ni][0], acc[mi][ni][1]);
                *(float2*)(Cf + dst + (size_t)8 * CDIM) = make_float2(acc[mi][ni][2], acc[mi][ni][3]);
            } else {
                size_t dst = (size_t)(gn >> 9) * ((size_t)MROWS * CDIM)
                           + (size_t)r * CDIM + (gn & 511);
#pragma unroll
                for (int half = 0; half < 2; half++) {
                    float x0 = acc[mi][ni][half * 2], x1 = acc[mi][ni][half * 2 + 1];
                    __half h0 = __float2half_rn(x0), h1 = __float2half_rn(x1);
                    __half2 hv; hv.x = h0; hv.y = h1;
                    __half2 lv;
                    lv.x = __float2half_rn(x0 - __half2float(h0));
                    lv.y = __float2half_rn(x1 - __half2float(h1));
                    size_t d2 = dst + (size_t)(half * 8) * CDIM;
                    *(__half2*)(Ch + d2) = hv;
                    *(__half2*)(Cl + d2) = lv;
                }
            }
        }
    }
}

// ---------------------------------------------------------------------------
// HMMA attention (fp16 2-term): block per (n,h), 8 warps x 16 q-rows.
// QK^T: Q hi/lo x K single. P·V: P single x V hi/lo.
// exp2 with log2(e)*0.125 folded into Q. Output fp16 hi/lo.
// Smem: 144B rows -> conflict-free ldmatrix, no swizzle. 5 tiles = ~92KB.
// ---------------------------------------------------------------------------
#define AT_LD 72
#define AT_ROWB 144
#define AT_TILE (128 * AT_ROWB)     // 18432
#define OFF_QHs 0
#define OFF_QLs (1 * AT_TILE)
#define OFF_KHs (2 * AT_TILE)
#define OFF_VHs (3 * AT_TILE)
#define OFF_VLs (4 * AT_TILE)
#define OFF_MKs (5 * AT_TILE)
#define OFF_INV (OFF_MKs + 128)
#define ATT2_SMEM (OFF_INV + 128)   // 92416

__global__ __launch_bounds__(256, 2) void attn2(const __half* __restrict__ Ph,
                                                const __half* __restrict__ Pl,
                                                const unsigned char* __restrict__ pm,
                                                __half* __restrict__ Ohi,
                                                __half* __restrict__ Olo)
{
    extern __shared__ __align__(1024) char smc[];
    const uint32_t sb = smem_to_u32(smc);
    float* invf = (float*)(smc + OFF_INV);
    unsigned char* mk = (unsigned char*)(smc + OFF_MKs);

    const int tid  = threadIdx.x;
    const int lane = tid & 31;
    const int wid  = tid >> 5;
    const int n = blockIdx.x, h = blockIdx.y;
    const int b = n >> 6, w = n & 63;

    const __half* Qh_g = Ph;
    const __half* Ql_g = Pl;
    const __half* Kh_g = Ph + (size_t)MROWS * CDIM;
    const __half* Kl_g = Pl + (size_t)MROWS * CDIM;
    const __half* Vh_g = Ph + (size_t)2 * MROWS * CDIM;
    const __half* Vl_g = Pl + (size_t)2 * MROWS * CDIM;

    if (tid < 32) invf[tid] = powf(10000.0f, -(float)tid * (1.0f / 32.0f));
    if (tid < 128) mk[tid] = pm[(size_t)b * TTOT + tid * WDIL + w];

    // V tiles (hi+lo) via cp.async: 128 rows x 8 16B-chunks each
    for (int t = tid; t < 1024; t += 256) {
        int row = t >> 3, ch = t & 7;
        size_t g = ((size_t)(b * TTOT + row * WDIL + w)) * CDIM + h * HDIM + ch * 8;
        CP_ASYNC16(sb + OFF_VHs + row * AT_ROWB + ch * 16, Vh_g + g);
        CP_ASYNC16(sb + OFF_VLs + row * AT_ROWB + ch * 16, Vl_g + g);
    }
    CP_COMMIT();
    __syncthreads();   // invf + mask ready

    // Q/K staging with RoPE; fold 0.125*log2(e) into Q. Q -> hi/lo, K -> single.
    const float QSCALE = 0.125f * 1.44269504088896f;
    __half* sQh = (__half*)(smc + OFF_QHs);
    __half* sQl = (__half*)(smc + OFF_QLs);
    __half* sKh = (__half*)(smc + OFF_KHs);
    for (int e = tid; e < 128 * 32; e += 256) {
        int s = e >> 5, d = e & 31;
        size_t rb = ((size_t)(b * TTOT + s * WDIL + w)) * CDIM + h * HDIM;
        float ang = (float)s * invf[d];
        float si, co;
        sincosf(ang, &si, &co);
        float q0 = __half2float(Qh_g[rb + d]) + __half2float(Ql_g[rb + d]);
        float q1 = __half2float(Qh_g[rb + d + 32]) + __half2float(Ql_g[rb + d + 32]);
        float k0 = __half2float(Kh_g[rb + d]) + __half2float(Kl_g[rb + d]);
        float k1 = __half2float(Kh_g[rb + d + 32]) + __half2float(Kl_g[rb + d + 32]);
        float qa = (q0 * co - q1 * si) * QSCALE;
        float qb = (q1 * co + q0 * si) * QSCALE;
        __half t;
        t = __float2half_rn(qa); sQh[s * AT_LD + d] = t;
        sQl[s * AT_LD + d] = __float2half_rn(qa - __half2float(t));
        t = __float2half_rn(qb); sQh[s * AT_LD + d + 32] = t;
        sQl[s * AT_LD + d + 32] = __float2half_rn(qb - __half2float(t));
        sKh[s * AT_LD + d]      = __float2half_rn(k0 * co - k1 * si);
        sKh[s * AT_LD + d + 32] = __float2half_rn(k1 * co + k0 * si);
    }
    cp_wait<0>();
    __syncthreads();

    // ===== QK^T: warp tile m16 x n128 x k64 =====
    const int qr = wid * 16;
    float c[16][4];
#pragma unroll
    for (int j = 0; j < 16; j++)
#pragma unroll
        for (int v = 0; v < 4; v++) c[j][v] = 0.0f;

#pragma unroll
    for (int kk = 0; kk < 4; kk++) {
        uint32_t ah[4], al[4];
        uint32_t abase = sb + OFF_QHs + (uint32_t)((qr + (lane & 15)) * AT_ROWB)
                       + kk * 32 + (lane >> 4) * 16;
        ldsm4(ah, abase);
        ldsm4(al, abase + AT_TILE);
#pragma unroll
        for (int g = 0; g < 8; g++) {
            uint32_t kaddr = sb + OFF_KHs + (uint32_t)((g * 16 + (lane & 15)) * AT_ROWB)
                           + kk * 32 + (lane >> 4) * 16;
            uint32_t th[4];
            ldsm4(th, kaddr);
            mma2(c[2*g],   ah, th[0], th[2]);
            mma2(c[2*g],   al, th[0], th[2]);
            mma2(c[2*g+1], ah, th[1], th[3]);
            mma2(c[2*g+1], al, th[1], th[3]);
        }
    }

    // ===== mask + softmax =====
    float mx0 = -1e30f, mx1 = -1e30f;
#pragma unroll
    for (int j = 0; j < 16; j++) {
        int n0 = j * 8 + (lane & 3) * 2;
        if (mk[n0])     { c[j][0] = -1e30f; c[j][2] = -1e30f; }
        if (mk[n0 + 1]) { c[j][1] = -1e30f; c[j][3] = -1e30f; }
        mx0 = fmaxf(mx0, fmaxf(c[j][0], c[j][1]));
        mx1 = fmaxf(mx1, fmaxf(c[j][2], c[j][3]));
    }
    mx0 = fmaxf(mx0, __shfl_xor_sync(~0u, mx0, 1));
    mx0 = fmaxf(mx0, __shfl_xor_sync(~0u, mx0, 2));
    mx1 = fmaxf(mx1, __shfl_xor_sync(~0u, mx1, 1));
    mx1 = fmaxf(mx1, __shfl_xor_sync(~0u, mx1, 2));
    float s0 = 0.0f, s1 = 0.0f;
#pragma unroll
    for (int j = 0; j < 16; j++) {
        c[j][0] = ex2f(c[j][0] - mx0); s0 += c[j][0];
        c[j][1] = ex2f(c[j][1] - mx0); s0 += c[j][1];
        c[j][2] = ex2f(c[j][2] - mx1); s1 += c[j][2];
        c[j][3] = ex2f(c[j][3] - mx1); s1 += c[j][3];
    }
    s0 += __shfl_xor_sync(~0u, s0, 1); s0 += __shfl_xor_sync(~0u, s0, 2);
    s1 += __shfl_xor_sync(~0u, s1, 1); s1 += __shfl_xor_sync(~0u, s1, 2);
    const float inv0 = 1.0f / s0, inv1 = 1.0f / s1;

    // ===== P @ V: m16 x n64 x k128 (P single fp16, V hi/lo) =====
    float o[8][4];
#pragma unroll
    for (int j = 0; j < 8; j++)
#pragma unroll
        for (int v = 0; v < 4; v++) o[j][v] = 0.0f;

#pragma unroll
    for (int t = 0; t < 8; t++) {
        uint32_t pa[4];
#pragma unroll
        for (int q = 0; q < 4; q++) {
            int jt = 2 * t + (q >> 1);
            pa[q] = packh(c[jt][(q & 1) * 2], c[jt][(q & 1) * 2 + 1]);
        }
#pragma unroll
        for (int gg = 0; gg < 4; gg++) {
            uint32_t vaddr = sb + OFF_VHs
                + (uint32_t)((t * 16 + (lane & 7) + ((lane >> 3) & 1) * 8) * AT_ROWB)
                + gg * 32 + (lane >> 4) * 16;
            uint32_t vh[4], vl[4];
            ldsm4t(vh, vaddr);
            ldsm4t(vl, vaddr + AT_TILE);
            mma2(o[2*gg],   pa, vh[0], vh[1]);
            mma2(o[2*gg],   pa, vl[0], vl[1]);
            mma2(o[2*gg+1], pa, vh[2], vh[3]);
            mma2(o[2*gg+1], pa, vl[2], vl[3]);
        }
    }

    // ===== epilogue: normalize, split hi/lo, store =====
    const int r0 = qr + (lane >> 2);
#pragma unroll
    for (int j2 = 0; j2 < 8; j2++) {
        int d0 = j2 * 8 + (lane & 3) * 2;
        size_t g0 = ((size_t)(b * TTOT + r0 * WDIL + w)) * CDIM + h * HDIM + d0;
        size_t g1 = g0 + (size_t)8 * WDIL * CDIM;
        float y0 = o[j2][0] * inv0, y1 = o[j2][1] * inv0;
        __half h0 = __float2half_rn(y0), h1 = __float2half_rn(y1);
        __half2 hv; hv.x = h0; hv.y = h1;
        __half2 lv;
        lv.x = __float2half_rn(y0 - __half2float(h0));
        lv.y = __float2half_rn(y1 - __half2float(h1));
        *(__half2*)(Ohi + g0) = hv;
        *(__half2*)(Olo + g0) = lv;
        float y2 = o[j2][2] * inv1, y3 = o[j2][3] * inv1;
        h0 = __float2half_rn(y2); h1 = __float2half_rn(y3);
        hv.x = h0; hv.y = h1;
        lv.x = __float2half_rn(y2 - __half2float(h0));
        lv.y = __float2half_rn(y3 - __half2float(h1));
        *(__half2*)(Ohi + g1) = hv;
        *(__half2*)(Olo + g1) = lv;
    }
}

// ---------------------------------------------------------------------------
// Launch
// ---------------------------------------------------------------------------
extern "C" void kernel_launch(void* const* d_in, const int* in_sizes, int n_in,
                              void* d_out, int out_size)
{
    const float*         x  = (const float*)d_in[0];
    const unsigned char* pm = (const unsigned char*)d_in[1];
    const float*         Wq = (const float*)d_in[2];
    const float*         Wk = (const float*)d_in[3];
    const float*         Wv = (const float*)d_in[4];
    const float*         Wo = (const float*)d_in[5];
    float*               out = (float*)d_out;

    __half *xhi, *xlo, *ohi, *olo, *bq, *bo, *ph, *pl;
    cudaGetSymbolAddress((void**)&xhi, g_xhi);
    cudaGetSymbolAddress((void**)&xlo, g_xlo);
    cudaGetSymbolAddress((void**)&ohi, g_Ohi);
    cudaGetSymbolAddress((void**)&olo, g_Olo);
    cudaGetSymbolAddress((void**)&bq, g_Bq);
    cudaGetSymbolAddress((void**)&bo, g_Bo);
    cudaGetSymbolAddress((void**)&ph, g_Ph);
    cudaGetSymbolAddress((void**)&pl, g_Pl);

    cudaFuncSetAttribute(tc_gemm<0>, cudaFuncAttributeMaxDynamicSharedMemorySize, GEMM_SMEM);
    cudaFuncSetAttribute(tc_gemm<1>, cudaFuncAttributeMaxDynamicSharedMemorySize, GEMM_SMEM);
    cudaFuncSetAttribute(attn2, cudaFuncAttributeMaxDynamicSharedMemorySize, ATT2_SMEM);

    // 1) conversions
    conv_x<<<(MROWS * CDIM) / (256 * 4), 256>>>(x, xhi, xlo);
    conv_wqkv<<<(3 * CDIM * CDIM) / 256, 256>>>(Wq, Wk, Wv, bq);
    conv_wo<<<(CDIM * CDIM) / 256, 256>>>(Wo, bo);

    // 2) fused QKV projection -> fp16 hi/lo (Q|K|V partitions)
    tc_gemm<0><<<dim3(12, MROWS / 128), 256, GEMM_SMEM>>>(xhi, xlo, bq,
                                                          nullptr, ph, pl);

    // 3) HMMA attention -> fp16 hi/lo O
    attn2<<<dim3(256, NHEAD), 256, ATT2_SMEM>>>(ph, pl, pm, ohi, olo);

    // 4) output projection -> d_out (f32)
    tc_gemm<1><<<dim3(4, MROWS / 128), 256, GEMM_SMEM>>>(ohi, olo, bo,
                                                         out, nullptr, nullptr);
}

// round 8
// speedup vs baseline: 3.0483x; 1.0083x over previous
#include <cuda_runtime.h>
#include <cuda_fp16.h>
#include <math.h>
#include <stdint.h>

// Problem constants: B=4, T=8192, C=512, W=64 -> S=128, N=256, heads=8, hd=64
#define BSZ   4
#define TTOT  8192
#define CDIM  512
#define WDIL  64
#define NHEAD 8
#define HDIM  64
#define MROWS (BSZ * TTOT)   // 32768

// ---------------------------------------------------------------------------
// Scratch (static device memory; no allocation allowed)
// ---------------------------------------------------------------------------
__device__ __align__(1024) __half g_xhi[(size_t)MROWS * CDIM];
__device__ __align__(1024) __half g_xlo[(size_t)MROWS * CDIM];
__device__ __align__(1024) __half g_Ohi[(size_t)MROWS * CDIM];
__device__ __align__(1024) __half g_Olo[(size_t)MROWS * CDIM];
__device__ __align__(1024) __half g_Bq[(size_t)3 * CDIM * CDIM];   // QKV W^T [1536,512] K-major, fp16
__device__ __align__(1024) __half g_Bo[(size_t)CDIM * CDIM];       // Wo^T [512,512] K-major, fp16
__device__ __align__(1024) __half g_Ph[(size_t)3 * MROWS * CDIM];  // Q|K|V hi
__device__ __align__(1024) __half g_Pl[(size_t)3 * MROWS * CDIM];  // Q|K|V lo

// ---------------------------------------------------------------------------
// PTX helpers (sm_80-class only: cp.async, ldmatrix, mma.sync)
// ---------------------------------------------------------------------------
__device__ __forceinline__ uint32_t smem_to_u32(const void* p) {
    uint32_t a;
    asm("{ .reg .u64 t; cvta.to.shared.u64 t, %1; cvt.u32.u64 %0, t; }" : "=r"(a) : "l"(p));
    return a;
}
#define CP_ASYNC16(smaddr, gptr) \
    asm volatile("cp.async.cg.shared.global [%0], [%1], 16;" :: "r"(smaddr), "l"(gptr) : "memory")
#define CP_COMMIT() asm volatile("cp.async.commit_group;" ::: "memory")
template <int N> __device__ __forceinline__ void cp_wait() {
    asm volatile("cp.async.wait_group %0;" :: "n"(N) : "memory");
}
__device__ __forceinline__ void ldsm4(uint32_t* r, uint32_t addr) {
    asm volatile("ldmatrix.sync.aligned.m8n8.x4.shared.b16 {%0,%1,%2,%3}, [%4];"
                 : "=r"(r[0]), "=r"(r[1]), "=r"(r[2]), "=r"(r[3]) : "r"(addr));
}
__device__ __forceinline__ void ldsm4t(uint32_t* r, uint32_t addr) {
    asm volatile("ldmatrix.sync.aligned.m8n8.x4.trans.shared.b16 {%0,%1,%2,%3}, [%4];"
                 : "=r"(r[0]), "=r"(r[1]), "=r"(r[2]), "=r"(r[3]) : "r"(addr));
}
__device__ __forceinline__ void mma2(float* d, const uint32_t* a, uint32_t b0, uint32_t b1) {
    asm volatile("mma.sync.aligned.m16n8k16.row.col.f32.f16.f16.f32 "
                 "{%0,%1,%2,%3}, {%4,%5,%6,%7}, {%8,%9}, {%0,%1,%2,%3};"
                 : "+f"(d[0]), "+f"(d[1]), "+f"(d[2]), "+f"(d[3])
                 : "r"(a[0]), "r"(a[1]), "r"(a[2]), "r"(a[3]), "r"(b0), "r"(b1));
}
__device__ __forceinline__ float ex2f(float x) {
    float y; asm("ex2.approx.ftz.f32 %0, %1;" : "=f"(y) : "f"(x)); return y;
}
__device__ __forceinline__ uint32_t packh(float x, float y) {
    __half2 t = __floats2half2_rn(x, y);
    return *(uint32_t*)&t;
}
#define SWZ64(off) ((off) ^ (((off) >> 3) & 0x30))

// ---------------------------------------------------------------------------
// Conversion kernels
// ---------------------------------------------------------------------------
__global__ void conv_x(const float* __restrict__ x,
                       __half* __restrict__ hi, __half* __restrict__ lo) {
    size_t i = ((size_t)blockIdx.x * 256 + threadIdx.x) * 4;
    float4 v = *(const float4*)(x + i);
    float vv[4] = {v.x, v.y, v.z, v.w};
    __half h[4], l[4];
#pragma unroll
    for (int j = 0; j < 4; j++) {
        h[j] = __float2half_rn(vv[j]);
        l[j] = __float2half_rn(vv[j] - __half2float(h[j]));
    }
    *(uint2*)(hi + i) = *(uint2*)h;
    *(uint2*)(lo + i) = *(uint2*)l;
}

__global__ void conv_wqkv(const float* __restrict__ Wq, const float* __restrict__ Wk,
                          const float* __restrict__ Wv, __half* __restrict__ bq) {
    int idx = blockIdx.x * 256 + threadIdx.x;        // over 1536*512
    int n = idx >> 9, k = idx & 511;
    const float* W = (n < 512) ? Wq : (n < 1024) ? Wk : Wv;
    bq[idx] = __float2half_rn(W[(size_t)k * 512 + (n & 511)]);
}

__global__ void conv_wo(const float* __restrict__ Wo, __half* __restrict__ bo) {
    int idx = blockIdx.x * 256 + threadIdx.x;        // over 512*512
    int n = idx >> 9, k = idx & 511;
    bo[idx] = __float2half_rn(Wo[(size_t)k * 512 + n]);
}

// ---------------------------------------------------------------------------
// fp16 2-term GEMM via mma.sync: C = (Ahi+Alo) @ Bfp16^T.
// Tile 128x256, 256 threads (8 warps of 64x64), Kc=32, 4-stage cp.async
// pipeline, one __syncthreads per chunk, SW64 swizzle. 1 CTA/SM with high
// register budget (no spill of acc+fragments) for dense MMA issue.
// OUTF32=1: f32 row-major out. OUTF32=0: fp16 hi/lo out, column n routed to
// partition (n>>9) (fused QKV).
// ---------------------------------------------------------------------------
#define KC 32
#define CHUNKS 16
#define GA_BYTES (128 * 64)                    // 8192 per A version
#define GB_BYTES (256 * 64)                    // 16384
#define STAGE_BYTES (2 * GA_BYTES + GB_BYTES)  // 32768
#define OFF_ALO  GA_BYTES
#define OFF_B    (2 * GA_BYTES)
#define GSTAGES 4
#define GEMM_SMEM (GSTAGES * STAGE_BYTES)      // 131072

template<int OUTF32>
__global__ __launch_bounds__(256, 1) void tc_gemm(const __half* __restrict__ Ahi,
                                                  const __half* __restrict__ Alo,
                                                  const __half* __restrict__ Bw,
                                                  float* __restrict__ Cf,
                                                  __half* __restrict__ Ch,
                                                  __half* __restrict__ Cl)
{
    extern __shared__ __align__(1024) char smv[];
    const uint32_t sb = smem_to_u32(smv);
    const int tid  = threadIdx.x;
    const int wid  = tid >> 5;
    const int lane = tid & 31;
    const int wm   = (wid & 1) * 64;       // 0/64
    const int wn   = (wid >> 1) * 64;      // 0/64/128/192

    const int m0 = blockIdx.y * 128;
    const int n0 = blockIdx.x * 256;

    float acc[4][8][4];
#pragma unroll
    for (int mi = 0; mi < 4; mi++)
#pragma unroll
        for (int ni = 0; ni < 8; ni++)
#pragma unroll
            for (int v = 0; v < 4; v++) acc[mi][ni][v] = 0.0f;

    // producer: A 512x2 chunks + B 1024 chunks = 8 cp.async per thread
    auto issue = [&](int c) {
        const uint32_t base = sb + (c % GSTAGES) * STAGE_BYTES;
        const int k0 = c * KC;
#pragma unroll
        for (int r = 0; r < 2; r++) {
            int idx = tid + r * 256;           // 0..511
            int arow = idx >> 2, ach = idx & 3;
            uint32_t off = SWZ64((uint32_t)(arow * 64 + ach * 16));
            size_t ga = (size_t)(m0 + arow) * CDIM + k0 + ach * 8;
            CP_ASYNC16(base + off, Ahi + ga);
            CP_ASYNC16(base + OFF_ALO + off, Alo + ga);
        }
#pragma unroll
        for (int r = 0; r < 4; r++) {
            int idx = tid + r * 256;           // 0..1023
            int brow = idx >> 2, bch = idx & 3;
            uint32_t off = SWZ64((uint32_t)(brow * 64 + bch * 16));
            size_t gb = (size_t)(n0 + brow) * CDIM + k0 + bch * 8;
            CP_ASYNC16(base + OFF_B + off, Bw + gb);
        }
        CP_COMMIT();
    };

    issue(0); issue(1); issue(2);

    const int lrow = lane & 15;
    const int lkh  = (lane >> 4) * 16;

    for (int c = 0; c < CHUNKS; c++) {
        if (c < CHUNKS - 2)       cp_wait<2>();
        else if (c == CHUNKS - 2) cp_wait<1>();
        else                      cp_wait<0>();
        __syncthreads();
        if (c + 3 < CHUNKS) issue(c + 3);

        const uint32_t base = sb + (c % GSTAGES) * STAGE_BYTES;
#pragma unroll
        for (int s = 0; s < 2; s++) {          // two k16 steps per chunk
            uint32_t ah[2][4], al[2][4], bf[8][2];
#pragma unroll
            for (int mi = 0; mi < 2; mi++) {
                uint32_t a = SWZ64((uint32_t)((wm + mi * 32 + lrow) * 64 + s * 32 + lkh));
                // note: two 16-row A groups per 32 rows loaded separately below
                (void)a;
            }
#pragma unroll
            for (int mi = 0; mi < 2; mi++) { }  // (placeholder removed by compiler)
            uint32_t ahf[4][4], alf[4][4];
#pragma unroll
            for (int mi = 0; mi < 4; mi++) {
                uint32_t a = SWZ64((uint32_t)((wm + mi * 16 + lrow) * 64 + s * 32 + lkh));
                ldsm4(ahf[mi], base + a);
                ldsm4(alf[mi], base + OFF_ALO + a);
            }
#pragma unroll
            for (int g = 0; g < 4; g++) {
                uint32_t a = SWZ64((uint32_t)((wn + g * 16 + lrow) * 64 + s * 32 + lkh));
                uint32_t t[4];
                ldsm4(t, base + OFF_B + a);
                bf[g*2][0] = t[0]; bf[g*2+1][0] = t[1];
                bf[g*2][1] = t[2]; bf[g*2+1][1] = t[3];
            }
#pragma unroll
            for (int mi = 0; mi < 4; mi++)
#pragma unroll
                for (int ni = 0; ni < 8; ni++) {
                    mma2(acc[mi][ni], ahf[mi], bf[ni][0], bf[ni][1]);
                    mma2(acc[mi][ni], alf[mi], bf[ni][0], bf[ni][1]);
                }
            (void)ah; (void)al;
        }
    }

#pragma unroll
    for (int mi = 0; mi < 4; mi++) {
        int r = m0 + wm + mi * 16 + (lane >> 2);
#pragma unroll
        for (int ni = 0; ni < 8; ni++) {
            int gn = n0 + wn + ni * 8 + (lane & 3) * 2;
            if (OUTF32) {
                size_t dst = (size_t)r * CDIM + gn;
                *(float2*)(Cf + dst) = make_float2(acc[mi][ni][0], acc[mi][ni][1]);
                *(float2*)(Cf + dst + (size_t)8 * CDIM) = make_float2(acc[mi][ni][2], acc[mi][ni][3]);
            } else {
                size_t dst = (size_t)(gn >> 9) * ((size_t)MROWS * CDIM)
                           + (size_t)r * CDIM + (gn & 511);
#pragma unroll
                for (int half = 0; half < 2; half++) {
                    float x0 = acc[mi][ni][half * 2], x1 = acc[mi][ni][half * 2 + 1];
                    __half h0 = __float2half_rn(x0), h1 = __float2half_rn(x1);
                    __half2 hv; hv.x = h0; hv.y = h1;
                    __half2 lv;
                    lv.x = __float2half_rn(x0 - __half2float(h0));
                    lv.y = __float2half_rn(x1 - __half2float(h1));
                    size_t d2 = dst + (size_t)(half * 8) * CDIM;
                    *(__half2*)(Ch + d2) = hv;
                    *(__half2*)(Cl + d2) = lv;
                }
            }
        }
    }
}

// ---------------------------------------------------------------------------
// HMMA attention (fp16 2-term): block per (n,h), 8 warps x 16 q-rows.
// QK^T: Q hi/lo x K single. P·V: P single x V hi/lo.
// exp2 with log2(e)*0.125 folded into Q. Output fp16 hi/lo.
// Smem: 144B rows -> conflict-free ldmatrix, no swizzle. 5 tiles = ~92KB.
// ---------------------------------------------------------------------------
#define AT_LD 72
#define AT_ROWB 144
#define AT_TILE (128 * AT_ROWB)     // 18432
#define OFF_QHs 0
#define OFF_QLs (1 * AT_TILE)
#define OFF_KHs (2 * AT_TILE)
#define OFF_VHs (3 * AT_TILE)
#define OFF_VLs (4 * AT_TILE)
#define OFF_MKs (5 * AT_TILE)
#define OFF_INV (OFF_MKs + 128)
#define ATT2_SMEM (OFF_INV + 128)   // 92416

__global__ __launch_bounds__(256, 2) void attn2(const __half* __restrict__ Ph,
                                                const __half* __restrict__ Pl,
                                                const unsigned char* __restrict__ pm,
                                                __half* __restrict__ Ohi,
                                                __half* __restrict__ Olo)
{
    extern __shared__ __align__(1024) char smc[];
    const uint32_t sb = smem_to_u32(smc);
    float* invf = (float*)(smc + OFF_INV);
    unsigned char* mk = (unsigned char*)(smc + OFF_MKs);

    const int tid  = threadIdx.x;
    const int lane = tid & 31;
    const int wid  = tid >> 5;
    const int n = blockIdx.x, h = blockIdx.y;
    const int b = n >> 6, w = n & 63;

    const __half* Qh_g = Ph;
    const __half* Ql_g = Pl;
    const __half* Kh_g = Ph + (size_t)MROWS * CDIM;
    const __half* Kl_g = Pl + (size_t)MROWS * CDIM;
    const __half* Vh_g = Ph + (size_t)2 * MROWS * CDIM;
    const __half* Vl_g = Pl + (size_t)2 * MROWS * CDIM;

    if (tid < 32) invf[tid] = powf(10000.0f, -(float)tid * (1.0f / 32.0f));
    if (tid < 128) mk[tid] = pm[(size_t)b * TTOT + tid * WDIL + w];

    // V tiles (hi+lo) via cp.async: 128 rows x 8 16B-chunks each
    for (int t = tid; t < 1024; t += 256) {
        int row = t >> 3, ch = t & 7;
        size_t g = ((size_t)(b * TTOT + row * WDIL + w)) * CDIM + h * HDIM + ch * 8;
        CP_ASYNC16(sb + OFF_VHs + row * AT_ROWB + ch * 16, Vh_g + g);
        CP_ASYNC16(sb + OFF_VLs + row * AT_ROWB + ch * 16, Vl_g + g);
    }
    CP_COMMIT();
    __syncthreads();   // invf + mask ready

    // Q/K staging with RoPE; fold 0.125*log2(e) into Q. Q -> hi/lo, K -> single.
    const float QSCALE = 0.125f * 1.44269504088896f;
    __half* sQh = (__half*)(smc + OFF_QHs);
    __half* sQl = (__half*)(smc + OFF_QLs);
    __half* sKh = (__half*)(smc + OFF_KHs);
    for (int e = tid; e < 128 * 32; e += 256) {
        int s = e >> 5, d = e & 31;
        size_t rb = ((size_t)(b * TTOT + s * WDIL + w)) * CDIM + h * HDIM;
        float ang = (float)s * invf[d];
        float si, co;
        sincosf(ang, &si, &co);
        float q0 = __half2float(Qh_g[rb + d]) + __half2float(Ql_g[rb + d]);
        float q1 = __half2float(Qh_g[rb + d + 32]) + __half2float(Ql_g[rb + d + 32]);
        float k0 = __half2float(Kh_g[rb + d]) + __half2float(Kl_g[rb + d]);
        float k1 = __half2float(Kh_g[rb + d + 32]) + __half2float(Kl_g[rb + d + 32]);
        float qa = (q0 * co - q1 * si) * QSCALE;
        float qb = (q1 * co + q0 * si) * QSCALE;
        __half t;
        t = __float2half_rn(qa); sQh[s * AT_LD + d] = t;
        sQl[s * AT_LD + d] = __float2half_rn(qa - __half2float(t));
        t = __float2half_rn(qb); sQh[s * AT_LD + d + 32] = t;
        sQl[s * AT_LD + d + 32] = __float2half_rn(qb - __half2float(t));
        sKh[s * AT_LD + d]      = __float2half_rn(k0 * co - k1 * si);
        sKh[s * AT_LD + d + 32] = __float2half_rn(k1 * co + k0 * si);
    }
    cp_wait<0>();
    __syncthreads();

    // ===== QK^T: warp tile m16 x n128 x k64 =====
    const int qr = wid * 16;
    float c[16][4];
#pragma unroll
    for (int j = 0; j < 16; j++)
#pragma unroll
        for (int v = 0; v < 4; v++) c[j][v] = 0.0f;

#pragma unroll
    for (int kk = 0; kk < 4; kk++) {
        uint32_t ah[4], al[4];
        uint32_t abase = sb + OFF_QHs + (uint32_t)((qr + (lane & 15)) * AT_ROWB)
                       + kk * 32 + (lane >> 4) * 16;
        ldsm4(ah, abase);
        ldsm4(al, abase + AT_TILE);
#pragma unroll
        for (int g = 0; g < 8; g++) {
            uint32_t kaddr = sb + OFF_KHs + (uint32_t)((g * 16 + (lane & 15)) * AT_ROWB)
                           + kk * 32 + (lane >> 4) * 16;
            uint32_t th[4];
            ldsm4(th, kaddr);
            mma2(c[2*g],   ah, th[0], th[2]);
            mma2(c[2*g],   al, th[0], th[2]);
            mma2(c[2*g+1], ah, th[1], th[3]);
            mma2(c[2*g+1], al, th[1], th[3]);
        }
    }

    // ===== mask + softmax =====
    float mx0 = -1e30f, mx1 = -1e30f;
#pragma unroll
    for (int j = 0; j < 16; j++) {
        int n0 = j * 8 + (lane & 3) * 2;
        if (mk[n0])     { c[j][0] = -1e30f; c[j][2] = -1e30f; }
        if (mk[n0 + 1]) { c[j][1] = -1e30f; c[j][3] = -1e30f; }
        mx0 = fmaxf(mx0, fmaxf(c[j][0], c[j][1]));
        mx1 = fmaxf(mx1, fmaxf(c[j][2], c[j][3]));
    }
    mx0 = fmaxf(mx0, __shfl_xor_sync(~0u, mx0, 1));
    mx0 = fmaxf(mx0, __shfl_xor_sync(~0u, mx0, 2));
    mx1 = fmaxf(mx1, __shfl_xor_sync(~0u, mx1, 1));
    mx1 = fmaxf(mx1, __shfl_xor_sync(~0u, mx1, 2));
    float s0 = 0.0f, s1 = 0.0f;
#pragma unroll
    for (int j = 0; j < 16; j++) {
        c[j][0] = ex2f(c[j][0] - mx0); s0 += c[j][0];
        c[j][1] = ex2f(c[j][1] - mx0); s0 += c[j][1];
        c[j][2] = ex2f(c[j][2] - mx1); s1 += c[j][2];
        c[j][3] = ex2f(c[j][3] - mx1); s1 += c[j][3];
    }
    s0 += __shfl_xor_sync(~0u, s0, 1); s0 += __shfl_xor_sync(~0u, s0, 2);
    s1 += __shfl_xor_sync(~0u, s1, 1); s1 += __shfl_xor_sync(~0u, s1, 2);
    const float inv0 = 1.0f / s0, inv1 = 1.0f / s1;

    // ===== P @ V: m16 x n64 x k128 (P single fp16, V hi/lo) =====
    float o[8][4];
#pragma unroll
    for (int j = 0; j < 8; j++)
#pragma unroll
        for (int v = 0; v < 4; v++) o[j][v] = 0.0f;

#pragma unroll
    for (int t = 0; t < 8; t++) {
        uint32_t pa[4];
#pragma unroll
        for (int q = 0; q < 4; q++) {
            int jt = 2 * t + (q >> 1);
            pa[q] = packh(c[jt][(q & 1) * 2], c[jt][(q & 1) * 2 + 1]);
        }
#pragma unroll
        for (int gg = 0; gg < 4; gg++) {
            uint32_t vaddr = sb + OFF_VHs
                + (uint32_t)((t * 16 + (lane & 7) + ((lane >> 3) & 1) * 8) * AT_ROWB)
                + gg * 32 + (lane >> 4) * 16;
            uint32_t vh[4], vl[4];
            ldsm4t(vh, vaddr);
            ldsm4t(vl, vaddr + AT_TILE);
            mma2(o[2*gg],   pa, vh[0], vh[1]);
            mma2(o[2*gg],   pa, vl[0], vl[1]);
            mma2(o[2*gg+1], pa, vh[2], vh[3]);
            mma2(o[2*gg+1], pa, vl[2], vl[3]);
        }
    }

    // ===== epilogue: normalize, split hi/lo, store =====
    const int r0 = qr + (lane >> 2);
#pragma unroll
    for (int j2 = 0; j2 < 8; j2++) {
        int d0 = j2 * 8 + (lane & 3) * 2;
        size_t g0 = ((size_t)(b * TTOT + r0 * WDIL + w)) * CDIM + h * HDIM + d0;
        size_t g1 = g0 + (size_t)8 * WDIL * CDIM;
        float y0 = o[j2][0] * inv0, y1 = o[j2][1] * inv0;
        __half h0 = __float2half_rn(y0), h1 = __float2half_rn(y1);
        __half2 hv; hv.x = h0; hv.y = h1;
        __half2 lv;
        lv.x = __float2half_rn(y0 - __half2float(h0));
        lv.y = __float2half_rn(y1 - __half2float(h1));
        *(__half2*)(Ohi + g0) = hv;
        *(__half2*)(Olo + g0) = lv;
        float y2 = o[j2][2] * inv1, y3 = o[j2][3] * inv1;
        h0 = __float2half_rn(y2); h1 = __float2half_rn(y3);
        hv.x = h0; hv.y = h1;
        lv.x = __float2half_rn(y2 - __half2float(h0));
        lv.y = __float2half_rn(y3 - __half2float(h1));
        *(__half2*)(Ohi + g1) = hv;
        *(__half2*)(Olo + g1) = lv;
    }
}

// ---------------------------------------------------------------------------
// Launch
// ---------------------------------------------------------------------------
extern "C" void kernel_launch(void* const* d_in, const int* in_sizes, int n_in,
                              void* d_out, int out_size)
{
    const float*         x  = (const float*)d_in[0];
    const unsigned char* pm = (const unsigned char*)d_in[1];
    const float*         Wq = (const float*)d_in[2];
    const float*         Wk = (const float*)d_in[3];
    const float*         Wv = (const float*)d_in[4];
    const float*         Wo = (const float*)d_in[5];
    float*               out = (float*)d_out;

    __half *xhi, *xlo, *ohi, *olo, *bq, *bo, *ph, *pl;
    cudaGetSymbolAddress((void**)&xhi, g_xhi);
    cudaGetSymbolAddress((void**)&xlo, g_xlo);
    cudaGetSymbolAddress((void**)&ohi, g_Ohi);
    cudaGetSymbolAddress((void**)&olo, g_Olo);
    cudaGetSymbolAddress((void**)&bq, g_Bq);
    cudaGetSymbolAddress((void**)&bo, g_Bo);
    cudaGetSymbolAddress((void**)&ph, g_Ph);
    cudaGetSymbolAddress((void**)&pl, g_Pl);

    cudaFuncSetAttribute(tc_gemm<0>, cudaFuncAttributeMaxDynamicSharedMemorySize, GEMM_SMEM);
    cudaFuncSetAttribute(tc_gemm<1>, cudaFuncAttributeMaxDynamicSharedMemorySize, GEMM_SMEM);
    cudaFuncSetAttribute(attn2, cudaFuncAttributeMaxDynamicSharedMemorySize, ATT2_SMEM);

    // 1) conversions
    conv_x<<<(MROWS * CDIM) / (256 * 4), 256>>>(x, xhi, xlo);
    conv_wqkv<<<(3 * CDIM * CDIM) / 256, 256>>>(Wq, Wk, Wv, bq);
    conv_wo<<<(CDIM * CDIM) / 256, 256>>>(Wo, bo);

    // 2) fused QKV projection -> fp16 hi/lo (Q|K|V partitions)
    tc_gemm<0><<<dim3(6, MROWS / 128), 256, GEMM_SMEM>>>(xhi, xlo, bq,
                                                         nullptr, ph, pl);

    // 3) HMMA attention -> fp16 hi/lo O
    attn2<<<dim3(256, NHEAD), 256, ATT2_SMEM>>>(ph, pl, pm, ohi, olo);

    // 4) output projection -> d_out (f32)
    tc_gemm<1><<<dim3(2, MROWS / 128), 256, GEMM_SMEM>>>(ohi, olo, bo,
                                                         out, nullptr, nullptr);
}

// round 9
// speedup vs baseline: 3.8375x; 1.2589x over previous
#include <cuda_runtime.h>
#include <cuda_fp16.h>
#include <math.h>
#include <stdint.h>

// Problem constants: B=4, T=8192, C=512, W=64 -> S=128, N=256, heads=8, hd=64
#define BSZ   4
#define TTOT  8192
#define CDIM  512
#define WDIL  64
#define NHEAD 8
#define HDIM  64
#define MROWS (BSZ * TTOT)   // 32768

// ---------------------------------------------------------------------------
// Scratch (static device memory; no allocation allowed)
// ---------------------------------------------------------------------------
__device__ __align__(1024) __half g_xh [(size_t)MROWS * CDIM];      // x fp16 (single)
__device__ __align__(1024) __half g_Ohi[(size_t)MROWS * CDIM];
__device__ __align__(1024) __half g_Olo[(size_t)MROWS * CDIM];
__device__ __align__(1024) __half g_Bq[(size_t)3 * CDIM * CDIM];    // QKV W^T [1536,512] K-major
__device__ __align__(1024) __half g_Bo[(size_t)CDIM * CDIM];        // Wo^T [512,512] K-major
__device__ __align__(1024) __half g_Ph[(size_t)3 * MROWS * CDIM];   // Q|K|V hi
__device__ __align__(1024) __half g_Pl[(size_t)3 * MROWS * CDIM];   // Q|K|V lo

// ---------------------------------------------------------------------------
// PTX helpers (sm_80-class only: cp.async, ldmatrix, mma.sync)
// ---------------------------------------------------------------------------
__device__ __forceinline__ uint32_t smem_to_u32(const void* p) {
    uint32_t a;
    asm("{ .reg .u64 t; cvta.to.shared.u64 t, %1; cvt.u32.u64 %0, t; }" : "=r"(a) : "l"(p));
    return a;
}
#define CP_ASYNC16(smaddr, gptr) \
    asm volatile("cp.async.cg.shared.global [%0], [%1], 16;" :: "r"(smaddr), "l"(gptr) : "memory")
#define CP_COMMIT() asm volatile("cp.async.commit_group;" ::: "memory")
template <int N> __device__ __forceinline__ void cp_wait() {
    asm volatile("cp.async.wait_group %0;" :: "n"(N) : "memory");
}
__device__ __forceinline__ void ldsm4(uint32_t* r, uint32_t addr) {
    asm volatile("ldmatrix.sync.aligned.m8n8.x4.shared.b16 {%0,%1,%2,%3}, [%4];"
                 : "=r"(r[0]), "=r"(r[1]), "=r"(r[2]), "=r"(r[3]) : "r"(addr));
}
__device__ __forceinline__ void ldsm4t(uint32_t* r, uint32_t addr) {
    asm volatile("ldmatrix.sync.aligned.m8n8.x4.trans.shared.b16 {%0,%1,%2,%3}, [%4];"
                 : "=r"(r[0]), "=r"(r[1]), "=r"(r[2]), "=r"(r[3]) : "r"(addr));
}
__device__ __forceinline__ void mma2(float* d, const uint32_t* a, uint32_t b0, uint32_t b1) {
    asm volatile("mma.sync.aligned.m16n8k16.row.col.f32.f16.f16.f32 "
                 "{%0,%1,%2,%3}, {%4,%5,%6,%7}, {%8,%9}, {%0,%1,%2,%3};"
                 : "+f"(d[0]), "+f"(d[1]), "+f"(d[2]), "+f"(d[3])
                 : "r"(a[0]), "r"(a[1]), "r"(a[2]), "r"(a[3]), "r"(b0), "r"(b1));
}
__device__ __forceinline__ float ex2f(float x) {
    float y; asm("ex2.approx.ftz.f32 %0, %1;" : "=f"(y) : "f"(x)); return y;
}
__device__ __forceinline__ uint32_t packh(float x, float y) {
    __half2 t = __floats2half2_rn(x, y);
    return *(uint32_t*)&t;
}
#define SWZ64(off) ((off) ^ (((off) >> 3) & 0x30))

// ---------------------------------------------------------------------------
// Conversion kernels
// ---------------------------------------------------------------------------
__global__ void conv_x(const float* __restrict__ x, __half* __restrict__ hx) {
    size_t i = ((size_t)blockIdx.x * 256 + threadIdx.x) * 4;
    float4 v = *(const float4*)(x + i);
    __half h[4];
    h[0] = __float2half_rn(v.x); h[1] = __float2half_rn(v.y);
    h[2] = __float2half_rn(v.z); h[3] = __float2half_rn(v.w);
    *(uint2*)(hx + i) = *(uint2*)h;
}

__global__ void conv_wqkv(const float* __restrict__ Wq, const float* __restrict__ Wk,
                          const float* __restrict__ Wv, __half* __restrict__ bq) {
    int idx = blockIdx.x * 256 + threadIdx.x;        // over 1536*512
    int n = idx >> 9, k = idx & 511;
    const float* W = (n < 512) ? Wq : (n < 1024) ? Wk : Wv;
    bq[idx] = __float2half_rn(W[(size_t)k * 512 + (n & 511)]);
}

__global__ void conv_wo(const float* __restrict__ Wo, __half* __restrict__ bo) {
    int idx = blockIdx.x * 256 + threadIdx.x;        // over 512*512
    int n = idx >> 9, k = idx & 511;
    bo[idx] = __float2half_rn(Wo[(size_t)k * 512 + n]);
}

// ---------------------------------------------------------------------------
// fp16 GEMM via mma.sync: C = A @ B^T (TERMS=1: single A; TERMS=2: A=Ahi+Alo).
// Tile 128x256, 256 threads (8 warps of 64x64), Kc=32, 4-stage cp.async
// pipeline, one __syncthreads per chunk, SW64 swizzle, 1 CTA/SM.
// TERMS=1 path preloads the whole chunk's fragments, then bursts 64 MMAs.
// OUTF32=1: f32 row-major out. OUTF32=0: fp16 hi/lo out, column n routed to
// partition (n>>9) (fused QKV).
// ---------------------------------------------------------------------------
#define KC 32
#define CHUNKS 16
#define GA_BYTES (128 * 64)                    // 8192 per A version
#define GB_BYTES (256 * 64)                    // 16384
#define GSTAGES 4

template<int OUTF32, int TERMS>
__global__ __launch_bounds__(256, 1) void tc_gemm(const __half* __restrict__ Ahi,
                                                  const __half* __restrict__ Alo,
                                                  const __half* __restrict__ Bw,
                                                  float* __restrict__ Cf,
                                                  __half* __restrict__ Ch,
                                                  __half* __restrict__ Cl)
{
    constexpr int STAGE_BYTES = TERMS * GA_BYTES + GB_BYTES;
    constexpr int OFF_ALO = GA_BYTES;                // valid when TERMS==2
    constexpr int OFF_B   = TERMS * GA_BYTES;

    extern __shared__ __align__(1024) char smv[];
    const uint32_t sb = smem_to_u32(smv);
    const int tid  = threadIdx.x;
    const int wid  = tid >> 5;
    const int lane = tid & 31;
    const int wm   = (wid & 1) * 64;       // 0/64
    const int wn   = (wid >> 1) * 64;      // 0/64/128/192

    const int m0 = blockIdx.y * 128;
    const int n0 = blockIdx.x * 256;

    float acc[4][8][4];
#pragma unroll
    for (int mi = 0; mi < 4; mi++)
#pragma unroll
        for (int ni = 0; ni < 8; ni++)
#pragma unroll
            for (int v = 0; v < 4; v++) acc[mi][ni][v] = 0.0f;

    auto issue = [&](int c) {
        const uint32_t base = sb + (c % GSTAGES) * STAGE_BYTES;
        const int k0 = c * KC;
#pragma unroll
        for (int r = 0; r < 2; r++) {
            int idx = tid + r * 256;           // 0..511
            int arow = idx >> 2, ach = idx & 3;
            uint32_t off = SWZ64((uint32_t)(arow * 64 + ach * 16));
            size_t ga = (size_t)(m0 + arow) * CDIM + k0 + ach * 8;
            CP_ASYNC16(base + off, Ahi + ga);
            if (TERMS == 2) CP_ASYNC16(base + OFF_ALO + off, Alo + ga);
        }
#pragma unroll
        for (int r = 0; r < 4; r++) {
            int idx = tid + r * 256;           // 0..1023
            int brow = idx >> 2, bch = idx & 3;
            uint32_t off = SWZ64((uint32_t)(brow * 64 + bch * 16));
            size_t gb = (size_t)(n0 + brow) * CDIM + k0 + bch * 8;
            CP_ASYNC16(base + OFF_B + off, Bw + gb);
        }
        CP_COMMIT();
    };

    issue(0); issue(1); issue(2);

    const int lrow = lane & 15;
    const int lkh  = (lane >> 4) * 16;

    for (int c = 0; c < CHUNKS; c++) {
        if (c < CHUNKS - 2)       cp_wait<2>();
        else if (c == CHUNKS - 2) cp_wait<1>();
        else                      cp_wait<0>();
        __syncthreads();
        if (c + 3 < CHUNKS) issue(c + 3);

        const uint32_t base = sb + (c % GSTAGES) * STAGE_BYTES;

        if (TERMS == 1) {
            // Preload ALL fragments for both k16 steps, then dense MMA burst.
            uint32_t af[2][4][4], bfr[2][8][2];
#pragma unroll
            for (int s = 0; s < 2; s++) {
#pragma unroll
                for (int mi = 0; mi < 4; mi++) {
                    uint32_t a = SWZ64((uint32_t)((wm + mi * 16 + lrow) * 64 + s * 32 + lkh));
                    ldsm4(af[s][mi], base + a);
                }
#pragma unroll
                for (int g = 0; g < 4; g++) {
                    uint32_t a = SWZ64((uint32_t)((wn + g * 16 + lrow) * 64 + s * 32 + lkh));
                    uint32_t t[4];
                    ldsm4(t, base + OFF_B + a);
                    bfr[s][g*2][0] = t[0]; bfr[s][g*2+1][0] = t[1];
                    bfr[s][g*2][1] = t[2]; bfr[s][g*2+1][1] = t[3];
                }
            }
#pragma unroll
            for (int s = 0; s < 2; s++)
#pragma unroll
                for (int mi = 0; mi < 4; mi++)
#pragma unroll
                    for (int ni = 0; ni < 8; ni++)
                        mma2(acc[mi][ni], af[s][mi], bfr[s][ni][0], bfr[s][ni][1]);
        } else {
#pragma unroll
            for (int s = 0; s < 2; s++) {
                uint32_t ahf[4][4], alf[4][4], bf[8][2];
#pragma unroll
                for (int mi = 0; mi < 4; mi++) {
                    uint32_t a = SWZ64((uint32_t)((wm + mi * 16 + lrow) * 64 + s * 32 + lkh));
                    ldsm4(ahf[mi], base + a);
                    ldsm4(alf[mi], base + OFF_ALO + a);
                }
#pragma unroll
                for (int g = 0; g < 4; g++) {
                    uint32_t a = SWZ64((uint32_t)((wn + g * 16 + lrow) * 64 + s * 32 + lkh));
                    uint32_t t[4];
                    ldsm4(t, base + OFF_B + a);
                    bf[g*2][0] = t[0]; bf[g*2+1][0] = t[1];
                    bf[g*2][1] = t[2]; bf[g*2+1][1] = t[3];
                }
#pragma unroll
                for (int mi = 0; mi < 4; mi++)
#pragma unroll
                    for (int ni = 0; ni < 8; ni++) {
                        mma2(acc[mi][ni], ahf[mi], bf[ni][0], bf[ni][1]);
                        mma2(acc[mi][ni], alf[mi], bf[ni][0], bf[ni][1]);
                    }
            }
        }
    }

#pragma unroll
    for (int mi = 0; mi < 4; mi++) {
        int r = m0 + wm + mi * 16 + (lane >> 2);
#pragma unroll
        for (int ni = 0; ni < 8; ni++) {
            int gn = n0 + wn + ni * 8 + (lane & 3) * 2;
            if (OUTF32) {
                size_t dst = (size_t)r * CDIM + gn;
                *(float2*)(Cf + dst) = make_float2(acc[mi][ni][0], acc[mi][ni][1]);
                *(float2*)(Cf + dst + (size_t)8 * CDIM) = make_float2(acc[mi][ni][2], acc[mi][ni][3]);
            } else {
                size_t dst = (size_t)(gn >> 9) * ((size_t)MROWS * CDIM)
                           + (size_t)r * CDIM + (gn & 511);
#pragma unroll
                for (int half = 0; half < 2; half++) {
                    float x0 = acc[mi][ni][half * 2], x1 = acc[mi][ni][half * 2 + 1];
                    __half h0 = __float2half_rn(x0), h1 = __float2half_rn(x1);
                    __half2 hv; hv.x = h0; hv.y = h1;
                    __half2 lv;
                    lv.x = __float2half_rn(x0 - __half2float(h0));
                    lv.y = __float2half_rn(x1 - __half2float(h1));
                    size_t d2 = dst + (size_t)(half * 8) * CDIM;
                    *(__half2*)(Ch + d2) = hv;
                    *(__half2*)(Cl + d2) = lv;
                }
            }
        }
    }
}

#define GEMM_SMEM_1 (GSTAGES * (1 * GA_BYTES + GB_BYTES))   // 98304
#define GEMM_SMEM_2 (GSTAGES * (2 * GA_BYTES + GB_BYTES))   // 131072

// ---------------------------------------------------------------------------
// HMMA attention (fp16 2-term): block per (n,h), 8 warps x 16 q-rows.
// QK^T: Q hi/lo x K single. P·V: P single x V hi/lo.
// exp2 with log2(e)*0.125 folded into Q. Output fp16 hi/lo.
// Smem: 144B rows -> conflict-free ldmatrix, no swizzle. 5 tiles = ~92KB.
// ---------------------------------------------------------------------------
#define AT_LD 72
#define AT_ROWB 144
#define AT_TILE (128 * AT_ROWB)     // 18432
#define OFF_QHs 0
#define OFF_QLs (1 * AT_TILE)
#define OFF_KHs (2 * AT_TILE)
#define OFF_VHs (3 * AT_TILE)
#define OFF_VLs (4 * AT_TILE)
#define OFF_MKs (5 * AT_TILE)
#define OFF_INV (OFF_MKs + 128)
#define ATT2_SMEM (OFF_INV + 128)   // 92416

__global__ __launch_bounds__(256, 2) void attn2(const __half* __restrict__ Ph,
                                                const __half* __restrict__ Pl,
                                                const unsigned char* __restrict__ pm,
                                                __half* __restrict__ Ohi,
                                                __half* __restrict__ Olo)
{
    extern __shared__ __align__(1024) char smc[];
    const uint32_t sb = smem_to_u32(smc);
    float* invf = (float*)(smc + OFF_INV);
    unsigned char* mk = (unsigned char*)(smc + OFF_MKs);

    const int tid  = threadIdx.x;
    const int lane = tid & 31;
    const int wid  = tid >> 5;
    const int n = blockIdx.x, h = blockIdx.y;
    const int b = n >> 6, w = n & 63;

    const __half* Qh_g = Ph;
    const __half* Ql_g = Pl;
    const __half* Kh_g = Ph + (size_t)MROWS * CDIM;
    const __half* Kl_g = Pl + (size_t)MROWS * CDIM;
    const __half* Vh_g = Ph + (size_t)2 * MROWS * CDIM;
    const __half* Vl_g = Pl + (size_t)2 * MROWS * CDIM;

    if (tid < 32) invf[tid] = powf(10000.0f, -(float)tid * (1.0f / 32.0f));
    if (tid < 128) mk[tid] = pm[(size_t)b * TTOT + tid * WDIL + w];

    // V tiles (hi+lo) via cp.async: 128 rows x 8 16B-chunks each
    for (int t = tid; t < 1024; t += 256) {
        int row = t >> 3, ch = t & 7;
        size_t g = ((size_t)(b * TTOT + row * WDIL + w)) * CDIM + h * HDIM + ch * 8;
        CP_ASYNC16(sb + OFF_VHs + row * AT_ROWB + ch * 16, Vh_g + g);
        CP_ASYNC16(sb + OFF_VLs + row * AT_ROWB + ch * 16, Vl_g + g);
    }
    CP_COMMIT();
    __syncthreads();   // invf + mask ready

    // Q/K staging with RoPE; fold 0.125*log2(e) into Q. Q -> hi/lo, K -> single.
    const float QSCALE = 0.125f * 1.44269504088896f;
    __half* sQh = (__half*)(smc + OFF_QHs);
    __half* sQl = (__half*)(smc + OFF_QLs);
    __half* sKh = (__half*)(smc + OFF_KHs);
    for (int e = tid; e < 128 * 32; e += 256) {
        int s = e >> 5, d = e & 31;
        size_t rb = ((size_t)(b * TTOT + s * WDIL + w)) * CDIM + h * HDIM;
        float ang = (float)s * invf[d];
        float si, co;
        sincosf(ang, &si, &co);
        float q0 = __half2float(Qh_g[rb + d]) + __half2float(Ql_g[rb + d]);
        float q1 = __half2float(Qh_g[rb + d + 32]) + __half2float(Ql_g[rb + d + 32]);
        float k0 = __half2float(Kh_g[rb + d]) + __half2float(Kl_g[rb + d]);
        float k1 = __half2float(Kh_g[rb + d + 32]) + __half2float(Kl_g[rb + d + 32]);
        float qa = (q0 * co - q1 * si) * QSCALE;
        float qb = (q1 * co + q0 * si) * QSCALE;
        __half t;
        t = __float2half_rn(qa); sQh[s * AT_LD + d] = t;
        sQl[s * AT_LD + d] = __float2half_rn(qa - __half2float(t));
        t = __float2half_rn(qb); sQh[s * AT_LD + d + 32] = t;
        sQl[s * AT_LD + d + 32] = __float2half_rn(qb - __half2float(t));
        sKh[s * AT_LD + d]      = __float2half_rn(k0 * co - k1 * si);
        sKh[s * AT_LD + d + 32] = __float2half_rn(k1 * co + k0 * si);
    }
    cp_wait<0>();
    __syncthreads();

    // ===== QK^T: warp tile m16 x n128 x k64 =====
    const int qr = wid * 16;
    float c[16][4];
#pragma unroll
    for (int j = 0; j < 16; j++)
#pragma unroll
        for (int v = 0; v < 4; v++) c[j][v] = 0.0f;

#pragma unroll
    for (int kk = 0; kk < 4; kk++) {
        uint32_t ah[4], al[4];
        uint32_t abase = sb + OFF_QHs + (uint32_t)((qr + (lane & 15)) * AT_ROWB)
                       + kk * 32 + (lane >> 4) * 16;
        ldsm4(ah, abase);
        ldsm4(al, abase + AT_TILE);
#pragma unroll
        for (int g = 0; g < 8; g++) {
            uint32_t kaddr = sb + OFF_KHs + (uint32_t)((g * 16 + (lane & 15)) * AT_ROWB)
                           + kk * 32 + (lane >> 4) * 16;
            uint32_t th[4];
            ldsm4(th, kaddr);
            mma2(c[2*g],   ah, th[0], th[2]);
            mma2(c[2*g],   al, th[0], th[2]);
            mma2(c[2*g+1], ah, th[1], th[3]);
            mma2(c[2*g+1], al, th[1], th[3]);
        }
    }

    // ===== mask + softmax =====
    float mx0 = -1e30f, mx1 = -1e30f;
#pragma unroll
    for (int j = 0; j < 16; j++) {
        int n0 = j * 8 + (lane & 3) * 2;
        if (mk[n0])     { c[j][0] = -1e30f; c[j][2] = -1e30f; }
        if (mk[n0 + 1]) { c[j][1] = -1e30f; c[j][3] = -1e30f; }
        mx0 = fmaxf(mx0, fmaxf(c[j][0], c[j][1]));
        mx1 = fmaxf(mx1, fmaxf(c[j][2], c[j][3]));
    }
    mx0 = fmaxf(mx0, __shfl_xor_sync(~0u, mx0, 1));
    mx0 = fmaxf(mx0, __shfl_xor_sync(~0u, mx0, 2));
    mx1 = fmaxf(mx1, __shfl_xor_sync(~0u, mx1, 1));
    mx1 = fmaxf(mx1, __shfl_xor_sync(~0u, mx1, 2));
    float s0 = 0.0f, s1 = 0.0f;
#pragma unroll
    for (int j = 0; j < 16; j++) {
        c[j][0] = ex2f(c[j][0] - mx0); s0 += c[j][0];
        c[j][1] = ex2f(c[j][1] - mx0); s0 += c[j][1];
        c[j][2] = ex2f(c[j][2] - mx1); s1 += c[j][2];
        c[j][3] = ex2f(c[j][3] - mx1); s1 += c[j][3];
    }
    s0 += __shfl_xor_sync(~0u, s0, 1); s0 += __shfl_xor_sync(~0u, s0, 2);
    s1 += __shfl_xor_sync(~0u, s1, 1); s1 += __shfl_xor_sync(~0u, s1, 2);
    const float inv0 = 1.0f / s0, inv1 = 1.0f / s1;

    // ===== P @ V: m16 x n64 x k128 (P single fp16, V hi/lo) =====
    float o[8][4];
#pragma unroll
    for (int j = 0; j < 8; j++)
#pragma unroll
        for (int v = 0; v < 4; v++) o[j][v] = 0.0f;

#pragma unroll
    for (int t = 0; t < 8; t++) {
        uint32_t pa[4];
#pragma unroll
        for (int q = 0; q < 4; q++) {
            int jt = 2 * t + (q >> 1);
            pa[q] = packh(c[jt][(q & 1) * 2], c[jt][(q & 1) * 2 + 1]);
        }
#pragma unroll
        for (int gg = 0; gg < 4; gg++) {
            uint32_t vaddr = sb + OFF_VHs
                + (uint32_t)((t * 16 + (lane & 7) + ((lane >> 3) & 1) * 8) * AT_ROWB)
                + gg * 32 + (lane >> 4) * 16;
            uint32_t vh[4], vl[4];
            ldsm4t(vh, vaddr);
            ldsm4t(vl, vaddr + AT_TILE);
            mma2(o[2*gg],   pa, vh[0], vh[1]);
            mma2(o[2*gg],   pa, vl[0], vl[1]);
            mma2(o[2*gg+1], pa, vh[2], vh[3]);
            mma2(o[2*gg+1], pa, vl[2], vl[3]);
        }
    }

    // ===== epilogue: normalize, split hi/lo, store =====
    const int r0 = qr + (lane >> 2);
#pragma unroll
    for (int j2 = 0; j2 < 8; j2++) {
        int d0 = j2 * 8 + (lane & 3) * 2;
        size_t g0 = ((size_t)(b * TTOT + r0 * WDIL + w)) * CDIM + h * HDIM + d0;
        size_t g1 = g0 + (size_t)8 * WDIL * CDIM;
        float y0 = o[j2][0] * inv0, y1 = o[j2][1] * inv0;
        __half h0 = __float2half_rn(y0), h1 = __float2half_rn(y1);
        __half2 hv; hv.x = h0; hv.y = h1;
        __half2 lv;
        lv.x = __float2half_rn(y0 - __half2float(h0));
        lv.y = __float2half_rn(y1 - __half2float(h1));
        *(__half2*)(Ohi + g0) = hv;
        *(__half2*)(Olo + g0) = lv;
        float y2 = o[j2][2] * inv1, y3 = o[j2][3] * inv1;
        h0 = __float2half_rn(y2); h1 = __float2half_rn(y3);
        hv.x = h0; hv.y = h1;
        lv.x = __float2half_rn(y2 - __half2float(h0));
        lv.y = __float2half_rn(y3 - __half2float(h1));
        *(__half2*)(Ohi + g1) = hv;
        *(__half2*)(Olo + g1) = lv;
    }
}

// ---------------------------------------------------------------------------
// Launch
// ---------------------------------------------------------------------------
extern "C" void kernel_launch(void* const* d_in, const int* in_sizes, int n_in,
                              void* d_out, int out_size)
{
    const float*         x  = (const float*)d_in[0];
    const unsigned char* pm = (const unsigned char*)d_in[1];
    const float*         Wq = (const float*)d_in[2];
    const float*         Wk = (const float*)d_in[3];
    const float*         Wv = (const float*)d_in[4];
    const float*         Wo = (const float*)d_in[5];
    float*               out = (float*)d_out;

    __half *xh, *ohi, *olo, *bq, *bo, *ph, *pl;
    cudaGetSymbolAddress((void**)&xh, g_xh);
    cudaGetSymbolAddress((void**)&ohi, g_Ohi);
    cudaGetSymbolAddress((void**)&olo, g_Olo);
    cudaGetSymbolAddress((void**)&bq, g_Bq);
    cudaGetSymbolAddress((void**)&bo, g_Bo);
    cudaGetSymbolAddress((void**)&ph, g_Ph);
    cudaGetSymbolAddress((void**)&pl, g_Pl);

    cudaFuncSetAttribute((const void*)tc_gemm<0,1>,
                         cudaFuncAttributeMaxDynamicSharedMemorySize, GEMM_SMEM_1);
    cudaFuncSetAttribute((const void*)tc_gemm<1,2>,
                         cudaFuncAttributeMaxDynamicSharedMemorySize, GEMM_SMEM_2);
    cudaFuncSetAttribute(attn2, cudaFuncAttributeMaxDynamicSharedMemorySize, ATT2_SMEM);

    // 1) conversions
    conv_x<<<(MROWS * CDIM) / (256 * 4), 256>>>(x, xh);
    conv_wqkv<<<(3 * CDIM * CDIM) / 256, 256>>>(Wq, Wk, Wv, bq);
    conv_wo<<<(CDIM * CDIM) / 256, 256>>>(Wo, bo);

    // 2) fused QKV projection (single-term A) -> fp16 hi/lo (Q|K|V partitions)
    tc_gemm<0,1><<<dim3(6, MROWS / 128), 256, GEMM_SMEM_1>>>(xh, nullptr, bq,
                                                             nullptr, ph, pl);

    // 3) HMMA attention -> fp16 hi/lo O
    attn2<<<dim3(256, NHEAD), 256, ATT2_SMEM>>>(ph, pl, pm, ohi, olo);

    // 4) output projection (2-term A = Ohi+Olo) -> d_out (f32)
    tc_gemm<1,2><<<dim3(2, MROWS / 128), 256, GEMM_SMEM_2>>>(ohi, olo, bo,
                                                             out, nullptr, nullptr);
}

// round 10
// speedup vs baseline: 5.0283x; 1.3103x over previous
#include <cuda_runtime.h>
#include <cuda_fp16.h>
#include <math.h>
#include <stdint.h>

// Problem constants: B=4, T=8192, C=512, W=64 -> S=128, N=256, heads=8, hd=64
#define BSZ   4
#define TTOT  8192
#define CDIM  512
#define WDIL  64
#define NHEAD 8
#define HDIM  64
#define MROWS (BSZ * TTOT)   // 32768

// ---------------------------------------------------------------------------
// Scratch (static device memory; no allocation allowed)
// ---------------------------------------------------------------------------
__device__ __align__(1024) __half g_xh[(size_t)MROWS * CDIM];      // x fp16
__device__ __align__(1024) float  g_Qf[(size_t)MROWS * CDIM];      // Q fp32
__device__ __align__(1024) __half g_Kh[(size_t)MROWS * CDIM];      // K fp16
__device__ __align__(1024) __half g_Vh[(size_t)MROWS * CDIM];      // V fp16
__device__ __align__(1024) __half g_Oh[(size_t)MROWS * CDIM];      // attn out fp16
__device__ __align__(1024) __half g_Bq[(size_t)3 * CDIM * CDIM];   // QKV W^T [1536,512] K-major
__device__ __align__(1024) __half g_Bo[(size_t)CDIM * CDIM];       // Wo^T [512,512] K-major

// ---------------------------------------------------------------------------
// PTX helpers (sm_80-class only: cp.async, ldmatrix, mma.sync)
// ---------------------------------------------------------------------------
__device__ __forceinline__ uint32_t smem_to_u32(const void* p) {
    uint32_t a;
    asm("{ .reg .u64 t; cvta.to.shared.u64 t, %1; cvt.u32.u64 %0, t; }" : "=r"(a) : "l"(p));
    return a;
}
#define CP_ASYNC16(smaddr, gptr) \
    asm volatile("cp.async.cg.shared.global [%0], [%1], 16;" :: "r"(smaddr), "l"(gptr) : "memory")
#define CP_COMMIT() asm volatile("cp.async.commit_group;" ::: "memory")
template <int N> __device__ __forceinline__ void cp_wait() {
    asm volatile("cp.async.wait_group %0;" :: "n"(N) : "memory");
}
__device__ __forceinline__ void ldsm4(uint32_t* r, uint32_t addr) {
    asm volatile("ldmatrix.sync.aligned.m8n8.x4.shared.b16 {%0,%1,%2,%3}, [%4];"
                 : "=r"(r[0]), "=r"(r[1]), "=r"(r[2]), "=r"(r[3]) : "r"(addr));
}
__device__ __forceinline__ void ldsm4t(uint32_t* r, uint32_t addr) {
    asm volatile("ldmatrix.sync.aligned.m8n8.x4.trans.shared.b16 {%0,%1,%2,%3}, [%4];"
                 : "=r"(r[0]), "=r"(r[1]), "=r"(r[2]), "=r"(r[3]) : "r"(addr));
}
__device__ __forceinline__ void mma2(float* d, const uint32_t* a, uint32_t b0, uint32_t b1) {
    asm volatile("mma.sync.aligned.m16n8k16.row.col.f32.f16.f16.f32 "
                 "{%0,%1,%2,%3}, {%4,%5,%6,%7}, {%8,%9}, {%0,%1,%2,%3};"
                 : "+f"(d[0]), "+f"(d[1]), "+f"(d[2]), "+f"(d[3])
                 : "r"(a[0]), "r"(a[1]), "r"(a[2]), "r"(a[3]), "r"(b0), "r"(b1));
}
__device__ __forceinline__ float ex2f(float x) {
    float y; asm("ex2.approx.ftz.f32 %0, %1;" : "=f"(y) : "f"(x)); return y;
}
__device__ __forceinline__ uint32_t packh(float x, float y) {
    __half2 t = __floats2half2_rn(x, y);
    return *(uint32_t*)&t;
}
#define SWZ64(off) ((off) ^ (((off) >> 3) & 0x30))

// ---------------------------------------------------------------------------
// Conversion kernels
// ---------------------------------------------------------------------------
__global__ void conv_x(const float* __restrict__ x, __half* __restrict__ hx) {
    size_t i = ((size_t)blockIdx.x * 256 + threadIdx.x) * 4;
    float4 v = *(const float4*)(x + i);
    __half h[4];
    h[0] = __float2half_rn(v.x); h[1] = __float2half_rn(v.y);
    h[2] = __float2half_rn(v.z); h[3] = __float2half_rn(v.w);
    *(uint2*)(hx + i) = *(uint2*)h;
}

__global__ void conv_wqkv(const float* __restrict__ Wq, const float* __restrict__ Wk,
                          const float* __restrict__ Wv, __half* __restrict__ bq) {
    int idx = blockIdx.x * 256 + threadIdx.x;        // over 1536*512
    int n = idx >> 9, k = idx & 511;
    const float* W = (n < 512) ? Wq : (n < 1024) ? Wk : Wv;
    bq[idx] = __float2half_rn(W[(size_t)k * 512 + (n & 511)]);
}

__global__ void conv_wo(const float* __restrict__ Wo, __half* __restrict__ bo) {
    int idx = blockIdx.x * 256 + threadIdx.x;        // over 512*512
    int n = idx >> 9, k = idx & 511;
    bo[idx] = __float2half_rn(Wo[(size_t)k * 512 + n]);
}

// ---------------------------------------------------------------------------
// fp16 GEMM via mma.sync: C = A @ B^T (single-term A).
// Tile 128x256, 256 threads (8 warps of 64x64), Kc=32, 4-stage cp.async
// pipeline, one __syncthreads per chunk, SW64 swizzle, 1 CTA/SM.
// QKV=0: f32 row-major out to Cf.
// QKV=1: per-partition out (which = n>>9): 0 -> Cq fp32, 1 -> Ck fp16,
//        2 -> Cv fp16 (single-rounded).
// ---------------------------------------------------------------------------
#define KC 32
#define CHUNKS 16
#define GA_BYTES (128 * 64)                    // 8192
#define GB_BYTES (256 * 64)                    // 16384
#define STAGE_BYTES (GA_BYTES + GB_BYTES)      // 24576
#define OFF_B   GA_BYTES
#define GSTAGES 4
#define GEMM_SMEM (GSTAGES * STAGE_BYTES)      // 98304

template<int QKV>
__global__ __launch_bounds__(256, 1) void tc_gemm(const __half* __restrict__ Aw,
                                                  const __half* __restrict__ Bw,
                                                  float* __restrict__ Cf,
                                                  float* __restrict__ Cq,
                                                  __half* __restrict__ Ck,
                                                  __half* __restrict__ Cv)
{
    extern __shared__ __align__(1024) char smv[];
    const uint32_t sb = smem_to_u32(smv);
    const int tid  = threadIdx.x;
    const int wid  = tid >> 5;
    const int lane = tid & 31;
    const int wm   = (wid & 1) * 64;       // 0/64
    const int wn   = (wid >> 1) * 64;      // 0/64/128/192

    const int m0 = blockIdx.y * 128;
    const int n0 = blockIdx.x * 256;

    float acc[4][8][4];
#pragma unroll
    for (int mi = 0; mi < 4; mi++)
#pragma unroll
        for (int ni = 0; ni < 8; ni++)
#pragma unroll
            for (int v = 0; v < 4; v++) acc[mi][ni][v] = 0.0f;

    auto issue = [&](int c) {
        const uint32_t base = sb + (c % GSTAGES) * STAGE_BYTES;
        const int k0 = c * KC;
#pragma unroll
        for (int r = 0; r < 2; r++) {
            int idx = tid + r * 256;           // 0..511
            int arow = idx >> 2, ach = idx & 3;
            uint32_t off = SWZ64((uint32_t)(arow * 64 + ach * 16));
            size_t ga = (size_t)(m0 + arow) * CDIM + k0 + ach * 8;
            CP_ASYNC16(base + off, Aw + ga);
        }
#pragma unroll
        for (int r = 0; r < 4; r++) {
            int idx = tid + r * 256;           // 0..1023
            int brow = idx >> 2, bch = idx & 3;
            uint32_t off = SWZ64((uint32_t)(brow * 64 + bch * 16));
            size_t gb = (size_t)(n0 + brow) * CDIM + k0 + bch * 8;
            CP_ASYNC16(base + OFF_B + off, Bw + gb);
        }
        CP_COMMIT();
    };

    issue(0); issue(1); issue(2);

    const int lrow = lane & 15;
    const int lkh  = (lane >> 4) * 16;

    for (int c = 0; c < CHUNKS; c++) {
        if (c < CHUNKS - 2)       cp_wait<2>();
        else if (c == CHUNKS - 2) cp_wait<1>();
        else                      cp_wait<0>();
        __syncthreads();
        if (c + 3 < CHUNKS) issue(c + 3);

        const uint32_t base = sb + (c % GSTAGES) * STAGE_BYTES;

        // Preload all fragments for both k16 steps, then dense MMA burst.
        uint32_t af[2][4][4], bfr[2][8][2];
#pragma unroll
        for (int s = 0; s < 2; s++) {
#pragma unroll
            for (int mi = 0; mi < 4; mi++) {
                uint32_t a = SWZ64((uint32_t)((wm + mi * 16 + lrow) * 64 + s * 32 + lkh));
                ldsm4(af[s][mi], base + a);
            }
#pragma unroll
            for (int g = 0; g < 4; g++) {
                uint32_t a = SWZ64((uint32_t)((wn + g * 16 + lrow) * 64 + s * 32 + lkh));
                uint32_t t[4];
                ldsm4(t, base + OFF_B + a);
                bfr[s][g*2][0] = t[0]; bfr[s][g*2+1][0] = t[1];
                bfr[s][g*2][1] = t[2]; bfr[s][g*2+1][1] = t[3];
            }
        }
#pragma unroll
        for (int s = 0; s < 2; s++)
#pragma unroll
            for (int mi = 0; mi < 4; mi++)
#pragma unroll
                for (int ni = 0; ni < 8; ni++)
                    mma2(acc[mi][ni], af[s][mi], bfr[s][ni][0], bfr[s][ni][1]);
    }

    // ---- epilogue ----
#pragma unroll
    for (int mi = 0; mi < 4; mi++) {
        int r = m0 + wm + mi * 16 + (lane >> 2);
#pragma unroll
        for (int ni = 0; ni < 8; ni++) {
            int gn = n0 + wn + ni * 8 + (lane & 3) * 2;
            if (!QKV) {
                size_t dst = (size_t)r * CDIM + gn;
                *(float2*)(Cf + dst) = make_float2(acc[mi][ni][0], acc[mi][ni][1]);
                *(float2*)(Cf + dst + (size_t)8 * CDIM) = make_float2(acc[mi][ni][2], acc[mi][ni][3]);
            } else {
                const int which = gn >> 9;      // uniform per CTA
                const int col = gn & 511;
                size_t dst = (size_t)r * CDIM + col;
                if (which == 0) {
                    *(float2*)(Cq + dst) = make_float2(acc[mi][ni][0], acc[mi][ni][1]);
                    *(float2*)(Cq + dst + (size_t)8 * CDIM) = make_float2(acc[mi][ni][2], acc[mi][ni][3]);
                } else {
                    __half* Cd = (which == 1) ? Ck : Cv;
                    __half2 h0; h0.x = __float2half_rn(acc[mi][ni][0]);
                                h0.y = __float2half_rn(acc[mi][ni][1]);
                    __half2 h1; h1.x = __float2half_rn(acc[mi][ni][2]);
                                h1.y = __float2half_rn(acc[mi][ni][3]);
                    *(__half2*)(Cd + dst) = h0;
                    *(__half2*)(Cd + dst + (size_t)8 * CDIM) = h1;
                }
            }
        }
    }
}

// ---------------------------------------------------------------------------
// HMMA attention: block per (n,h), 8 warps x 16 q-rows.
// QK^T: Q hi/lo (from fp32 input) x K single. P·V: P single x V single.
// exp2 with log2(e)*0.125 folded into Q. Output single fp16.
// Smem: 144B rows -> conflict-free ldmatrix, no swizzle. 4 tiles = ~74KB.
// ---------------------------------------------------------------------------
#define AT_LD 72
#define AT_ROWB 144
#define AT_TILE (128 * AT_ROWB)     // 18432
#define OFF_QHs 0
#define OFF_QLs (1 * AT_TILE)
#define OFF_KHs (2 * AT_TILE)
#define OFF_VHs (3 * AT_TILE)
#define OFF_MKs (4 * AT_TILE)       // 73728
#define OFF_INV (OFF_MKs + 128)
#define ATT2_SMEM (OFF_INV + 128)   // 73984

__global__ __launch_bounds__(256, 2) void attn2(const float* __restrict__ Qf,
                                                const __half* __restrict__ Kg,
                                                const __half* __restrict__ Vg,
                                                const unsigned char* __restrict__ pm,
                                                __half* __restrict__ Oh)
{
    extern __shared__ __align__(1024) char smc[];
    const uint32_t sb = smem_to_u32(smc);
    float* invf = (float*)(smc + OFF_INV);
    unsigned char* mk = (unsigned char*)(smc + OFF_MKs);

    const int tid  = threadIdx.x;
    const int lane = tid & 31;
    const int wid  = tid >> 5;
    const int n = blockIdx.x, h = blockIdx.y;
    const int b = n >> 6, w = n & 63;

    if (tid < 32) invf[tid] = powf(10000.0f, -(float)tid * (1.0f / 32.0f));
    if (tid < 128) mk[tid] = pm[(size_t)b * TTOT + tid * WDIL + w];

    // V tile (single fp16): 128 rows x 8 16B-chunks
    for (int t = tid; t < 1024; t += 256) {
        int row = t >> 3, ch = t & 7;
        size_t g = ((size_t)(b * TTOT + row * WDIL + w)) * CDIM + h * HDIM + ch * 8;
        CP_ASYNC16(sb + OFF_VHs + row * AT_ROWB + ch * 16, Vg + g);
    }
    CP_COMMIT();
    __syncthreads();   // invf + mask ready

    // Q/K staging with RoPE; fold 0.125*log2(e) into Q. Q -> hi/lo, K -> single.
    const float QSCALE = 0.125f * 1.44269504088896f;
    __half* sQh = (__half*)(smc + OFF_QHs);
    __half* sQl = (__half*)(smc + OFF_QLs);
    __half* sKh = (__half*)(smc + OFF_KHs);
    for (int e = tid; e < 128 * 32; e += 256) {
        int s = e >> 5, d = e & 31;
        size_t rb = ((size_t)(b * TTOT + s * WDIL + w)) * CDIM + h * HDIM;
        float ang = (float)s * invf[d];
        float si, co;
        sincosf(ang, &si, &co);
        float q0 = Qf[rb + d];
        float q1 = Qf[rb + d + 32];
        float k0 = __half2float(Kg[rb + d]);
        float k1 = __half2float(Kg[rb + d + 32]);
        float qa = (q0 * co - q1 * si) * QSCALE;
        float qb = (q1 * co + q0 * si) * QSCALE;
        __half t;
        t = __float2half_rn(qa); sQh[s * AT_LD + d] = t;
        sQl[s * AT_LD + d] = __float2half_rn(qa - __half2float(t));
        t = __float2half_rn(qb); sQh[s * AT_LD + d + 32] = t;
        sQl[s * AT_LD + d + 32] = __float2half_rn(qb - __half2float(t));
        sKh[s * AT_LD + d]      = __float2half_rn(k0 * co - k1 * si);
        sKh[s * AT_LD + d + 32] = __float2half_rn(k1 * co + k0 * si);
    }
    cp_wait<0>();
    __syncthreads();

    // ===== QK^T: warp tile m16 x n128 x k64 =====
    const int qr = wid * 16;
    float c[16][4];
#pragma unroll
    for (int j = 0; j < 16; j++)
#pragma unroll
        for (int v = 0; v < 4; v++) c[j][v] = 0.0f;

#pragma unroll
    for (int kk = 0; kk < 4; kk++) {
        uint32_t ah[4], al[4];
        uint32_t abase = sb + OFF_QHs + (uint32_t)((qr + (lane & 15)) * AT_ROWB)
                       + kk * 32 + (lane >> 4) * 16;
        ldsm4(ah, abase);
        ldsm4(al, abase + AT_TILE);
#pragma unroll
        for (int g = 0; g < 8; g++) {
            uint32_t kaddr = sb + OFF_KHs + (uint32_t)((g * 16 + (lane & 15)) * AT_ROWB)
                           + kk * 32 + (lane >> 4) * 16;
            uint32_t th[4];
            ldsm4(th, kaddr);
            mma2(c[2*g],   ah, th[0], th[2]);
            mma2(c[2*g],   al, th[0], th[2]);
            mma2(c[2*g+1], ah, th[1], th[3]);
            mma2(c[2*g+1], al, th[1], th[3]);
        }
    }

    // ===== mask + softmax =====
    float mx0 = -1e30f, mx1 = -1e30f;
#pragma unroll
    for (int j = 0; j < 16; j++) {
        int n0 = j * 8 + (lane & 3) * 2;
        if (mk[n0])     { c[j][0] = -1e30f; c[j][2] = -1e30f; }
        if (mk[n0 + 1]) { c[j][1] = -1e30f; c[j][3] = -1e30f; }
        mx0 = fmaxf(mx0, fmaxf(c[j][0], c[j][1]));
        mx1 = fmaxf(mx1, fmaxf(c[j][2], c[j][3]));
    }
    mx0 = fmaxf(mx0, __shfl_xor_sync(~0u, mx0, 1));
    mx0 = fmaxf(mx0, __shfl_xor_sync(~0u, mx0, 2));
    mx1 = fmaxf(mx1, __shfl_xor_sync(~0u, mx1, 1));
    mx1 = fmaxf(mx1, __shfl_xor_sync(~0u, mx1, 2));
    float s0 = 0.0f, s1 = 0.0f;
#pragma unroll
    for (int j = 0; j < 16; j++) {
        c[j][0] = ex2f(c[j][0] - mx0); s0 += c[j][0];
        c[j][1] = ex2f(c[j][1] - mx0); s0 += c[j][1];
        c[j][2] = ex2f(c[j][2] - mx1); s1 += c[j][2];
        c[j][3] = ex2f(c[j][3] - mx1); s1 += c[j][3];
    }
    s0 += __shfl_xor_sync(~0u, s0, 1); s0 += __shfl_xor_sync(~0u, s0, 2);
    s1 += __shfl_xor_sync(~0u, s1, 1); s1 += __shfl_xor_sync(~0u, s1, 2);
    const float inv0 = 1.0f / s0, inv1 = 1.0f / s1;

    // ===== P @ V: m16 x n64 x k128 (P single fp16, V single) =====
    float o[8][4];
#pragma unroll
    for (int j = 0; j < 8; j++)
#pragma unroll
        for (int v = 0; v < 4; v++) o[j][v] = 0.0f;

#pragma unroll
    for (int t = 0; t < 8; t++) {
        uint32_t pa[4];
#pragma unroll
        for (int q = 0; q < 4; q++) {
            int jt = 2 * t + (q >> 1);
            pa[q] = packh(c[jt][(q & 1) * 2], c[jt][(q & 1) * 2 + 1]);
        }
#pragma unroll
        for (int gg = 0; gg < 4; gg++) {
            uint32_t vaddr = sb + OFF_VHs
                + (uint32_t)((t * 16 + (lane & 7) + ((lane >> 3) & 1) * 8) * AT_ROWB)
                + gg * 32 + (lane >> 4) * 16;
            uint32_t vh[4];
            ldsm4t(vh, vaddr);
            mma2(o[2*gg],   pa, vh[0], vh[1]);
            mma2(o[2*gg+1], pa, vh[2], vh[3]);
        }
    }

    // ===== epilogue: normalize, single fp16 store =====
    const int r0 = qr + (lane >> 2);
#pragma unroll
    for (int j2 = 0; j2 < 8; j2++) {
        int d0 = j2 * 8 + (lane & 3) * 2;
        size_t g0 = ((size_t)(b * TTOT + r0 * WDIL + w)) * CDIM + h * HDIM + d0;
        size_t g1 = g0 + (size_t)8 * WDIL * CDIM;
        __half2 hv;
        hv.x = __float2half_rn(o[j2][0] * inv0);
        hv.y = __float2half_rn(o[j2][1] * inv0);
        *(__half2*)(Oh + g0) = hv;
        hv.x = __float2half_rn(o[j2][2] * inv1);
        hv.y = __float2half_rn(o[j2][3] * inv1);
        *(__half2*)(Oh + g1) = hv;
    }
}

// ---------------------------------------------------------------------------
// Launch
// ---------------------------------------------------------------------------
extern "C" void kernel_launch(void* const* d_in, const int* in_sizes, int n_in,
                              void* d_out, int out_size)
{
    const float*         x  = (const float*)d_in[0];
    const unsigned char* pm = (const unsigned char*)d_in[1];
    const float*         Wq = (const float*)d_in[2];
    const float*         Wk = (const float*)d_in[3];
    const float*         Wv = (const float*)d_in[4];
    const float*         Wo = (const float*)d_in[5];
    float*               out = (float*)d_out;

    __half *xh, *kh, *vh, *oh, *bq, *bo;
    float *qf;
    cudaGetSymbolAddress((void**)&xh, g_xh);
    cudaGetSymbolAddress((void**)&qf, g_Qf);
    cudaGetSymbolAddress((void**)&kh, g_Kh);
    cudaGetSymbolAddress((void**)&vh, g_Vh);
    cudaGetSymbolAddress((void**)&oh, g_Oh);
    cudaGetSymbolAddress((void**)&bq, g_Bq);
    cudaGetSymbolAddress((void**)&bo, g_Bo);

    cudaFuncSetAttribute((const void*)tc_gemm<1>,
                         cudaFuncAttributeMaxDynamicSharedMemorySize, GEMM_SMEM);
    cudaFuncSetAttribute((const void*)tc_gemm<0>,
                         cudaFuncAttributeMaxDynamicSharedMemorySize, GEMM_SMEM);
    cudaFuncSetAttribute(attn2, cudaFuncAttributeMaxDynamicSharedMemorySize, ATT2_SMEM);

    // 1) conversions
    conv_x<<<(MROWS * CDIM) / (256 * 4), 256>>>(x, xh);
    conv_wqkv<<<(3 * CDIM * CDIM) / 256, 256>>>(Wq, Wk, Wv, bq);
    conv_wo<<<(CDIM * CDIM) / 256, 256>>>(Wo, bo);

    // 2) fused QKV projection -> Q fp32 | K fp16 | V fp16
    tc_gemm<1><<<dim3(6, MROWS / 128), 256, GEMM_SMEM>>>(xh, bq,
                                                         nullptr, qf, kh, vh);

    // 3) HMMA attention -> O fp16
    attn2<<<dim3(256, NHEAD), 256, ATT2_SMEM>>>(qf, kh, vh, pm, oh);

    // 4) output projection (single-term A = Oh) -> d_out (f32)
    tc_gemm<0><<<dim3(2, MROWS / 128), 256, GEMM_SMEM>>>(oh, bo,
                                                         out, nullptr, nullptr, nullptr);
}